// round 2
// baseline (speedup 1.0000x reference)
#include <cuda_runtime.h>
#include <cstdint>

#define NN 32768
#define DD 128
#define DIc 256
#define DSc 16
#define LC 128
#define NCH (NN / LC)
#define EPSF 1e-5f
#define LOG2E 1.4426950408889634f

// ---------------- scratch (device globals; no allocation allowed) -------------
__device__ float g_resid[NN * DD];
__device__ float g_rms[NN * DD];
__device__ float g_xz[NN * 2 * DIc];
__device__ float g_xc[NN * DIc];
__device__ float g_dbc[NN * 64];
__device__ float g_dt[NN * DIc];
__device__ float g_Bm[NN * DSc];
__device__ float g_Cm[NN * DSc];
__device__ float g_P[NCH * DIc * DSc];
__device__ float g_He[NCH * DIc * DSc];
__device__ float g_Hin[NCH * DIc * DSc];
__device__ float g_y[NN * DIc];
__device__ float g_x2[NN * DD];
__device__ float g_xw64[DIc * 64];

// ---------------- helpers -----------------------------------------------------
__device__ __forceinline__ float ex2(float x) {
    float y;
    asm("ex2.approx.ftz.f32 %0, %1;" : "=f"(y) : "f"(x));
    return y;
}
__device__ __forceinline__ float fexp(float x) { return ex2(x * LOG2E); }
__device__ __forceinline__ float silu_f(float x) { return x / (1.0f + fexp(-x)); }
__device__ __forceinline__ float softplus_f(float v) {
    if (v > 20.0f) return v;
    return log1pf(expf(v));
}

// ---------------- kernel 0: pad x_proj weights to 64 cols ---------------------
__global__ void k_wpad(const float* __restrict__ xw) {
    int idx = blockIdx.x * blockDim.x + threadIdx.x;
    if (idx < DIc * 64) {
        int k = idx >> 6, j = idx & 63;
        g_xw64[idx] = (j < 40) ? xw[k * 40 + j] : 0.0f;
    }
}

// ---------------- kernel 1: pos-encode + gather(perm) + RMSNorm ---------------
__global__ void k_pre(const float* __restrict__ vf, const int* __restrict__ coords,
                      const int* __restrict__ perm, const float* __restrict__ pos_w,
                      const float* __restrict__ pos_b, const float* __restrict__ rms_w) {
    int i = blockIdx.x;
    int d = threadIdx.x;  // 128
    int j = perm[i];
    int cz = coords[j * 4 + 1];
    int cy = coords[j * 4 + 2];
    int cx = coords[j * 4 + 3];
    const float dnm = 1.0f / 43.0f;   // Yc//12 + 1 = 43
    const float t12 = 1.0f / 12.0f;
    float pf[9];
    pf[0] = (float)cz * (1.0f / 16.0f);
    pf[1] = (float)(cy / 12) * dnm;
    pf[2] = (float)(cx / 12) * dnm;
    pf[3] = (float)(cy % 12) * t12;
    pf[4] = (float)(cx % 12) * t12;
    pf[5] = (float)((cy + 6) / 12) * dnm;
    pf[6] = (float)((cx + 6) / 12) * dnm;
    pf[7] = (float)((cy + 6) % 12) * t12;
    pf[8] = (float)((cx + 6) % 12) * t12;
    float pe = pos_b[d];
#pragma unroll
    for (int f = 0; f < 9; f++) pe = fmaf(pf[f], pos_w[f * DD + d], pe);
    float val = vf[(size_t)j * DD + d] + pe;
    g_resid[(size_t)i * DD + d] = val;

    float v2 = val * val;
#pragma unroll
    for (int o = 16; o > 0; o >>= 1) v2 += __shfl_xor_sync(0xffffffffu, v2, o);
    __shared__ float red[4];
    if ((d & 31) == 0) red[d >> 5] = v2;
    __syncthreads();
    float ms = (red[0] + red[1] + red[2] + red[3]) * (1.0f / 128.0f);
    g_rms[(size_t)i * DD + d] = val * rsqrtf(ms + EPSF) * rms_w[d];
}

// ---------------- generic tiled SGEMM (row-major): C = A@B (+ S) --------------
template <int BM, int BN, int BK, int TM, int TN, bool ADD>
__global__ void sgemm(const float* __restrict__ A, const float* __restrict__ B,
                      const float* __restrict__ S, float* __restrict__ C, int Nc, int Kd) {
    __shared__ float As[BK][BM];
    __shared__ float Bs[BK][BN];
    constexpr int NT = (BM / TM) * (BN / TN);  // 256
    int tid = threadIdx.x;
    int tCol = tid % (BN / TN);
    int tRow = tid / (BN / TN);
    long row0 = (long)blockIdx.x * BM;
    int col0 = blockIdx.y * BN;
    float acc[TM][TN];
#pragma unroll
    for (int i = 0; i < TM; i++)
#pragma unroll
        for (int j = 0; j < TN; j++) acc[i][j] = 0.0f;

    for (int k0 = 0; k0 < Kd; k0 += BK) {
#pragma unroll
        for (int it = 0; it < (BM * BK) / (4 * NT); it++) {
            int v = tid + it * NT;
            int r = v / (BK / 4);
            int c = (v % (BK / 4)) * 4;
            float4 f = *(const float4*)(A + (row0 + r) * Kd + k0 + c);
            As[c + 0][r] = f.x;
            As[c + 1][r] = f.y;
            As[c + 2][r] = f.z;
            As[c + 3][r] = f.w;
        }
#pragma unroll
        for (int it = 0; it < (BK * BN) / (4 * NT); it++) {
            int v = tid + it * NT;
            int r = v / (BN / 4);
            int c = (v % (BN / 4)) * 4;
            *(float4*)(&Bs[r][c]) = *(const float4*)(B + (long)(k0 + r) * Nc + col0 + c);
        }
        __syncthreads();
#pragma unroll
        for (int k = 0; k < BK; k++) {
            float a[TM], b[TN];
#pragma unroll
            for (int i = 0; i < TM; i += 4) {
                float4 f = *(const float4*)(&As[k][tRow * TM + i]);
                a[i] = f.x; a[i + 1] = f.y; a[i + 2] = f.z; a[i + 3] = f.w;
            }
#pragma unroll
            for (int j = 0; j < TN; j += 4) {
                float4 f = *(const float4*)(&Bs[k][tCol * TN + j]);
                b[j] = f.x; b[j + 1] = f.y; b[j + 2] = f.z; b[j + 3] = f.w;
            }
#pragma unroll
            for (int i = 0; i < TM; i++)
#pragma unroll
                for (int j = 0; j < TN; j++) acc[i][j] = fmaf(a[i], b[j], acc[i][j]);
        }
        __syncthreads();
    }
#pragma unroll
    for (int i = 0; i < TM; i++) {
        long r = row0 + tRow * TM + i;
#pragma unroll
        for (int j = 0; j < TN; j += 4) {
            long off = r * Nc + col0 + tCol * TN + j;
            float4 v;
            v.x = acc[i][j]; v.y = acc[i][j + 1]; v.z = acc[i][j + 2]; v.w = acc[i][j + 3];
            if (ADD) {
                float4 s = *(const float4*)(S + off);
                v.x += s.x; v.y += s.y; v.z += s.z; v.w += s.w;
            }
            *(float4*)(C + off) = v;
        }
    }
}

// ---------------- kernel 3: causal conv (K=4) + bias + silu -------------------
__global__ void k_conv(const float* __restrict__ conv_w, const float* __restrict__ conv_b) {
    int idx = blockIdx.x * blockDim.x + threadIdx.x;  // N*DI
    int t = idx >> 8;
    int c = idx & 255;
    float w0 = conv_w[c * 4 + 0], w1 = conv_w[c * 4 + 1];
    float w2 = conv_w[c * 4 + 2], w3 = conv_w[c * 4 + 3];
    float s = conv_b[c];
    if (t >= 3) {
        const float* p = g_xz + (size_t)(t - 3) * 512 + c;
        s = fmaf(w0, p[0], s);
        s = fmaf(w1, p[512], s);
        s = fmaf(w2, p[1024], s);
        s = fmaf(w3, p[1536], s);
    } else {
        if (t - 3 >= 0) s = fmaf(w0, g_xz[(size_t)(t - 3) * 512 + c], s);
        if (t - 2 >= 0) s = fmaf(w1, g_xz[(size_t)(t - 2) * 512 + c], s);
        if (t - 1 >= 0) s = fmaf(w2, g_xz[(size_t)(t - 1) * 512 + c], s);
        s = fmaf(w3, g_xz[(size_t)t * 512 + c], s);
    }
    g_xc[idx] = silu_f(s);
}

// ---------------- kernel 5: dt = softplus(dbc[:, :8] @ dt_w + dt_b) -----------
__global__ void k_dt(const float* __restrict__ dtw, const float* __restrict__ dtb) {
    int idx = blockIdx.x * blockDim.x + threadIdx.x;  // N*64
    int t = idx >> 6;
    int c4 = (idx & 63) * 4;
    float4 d0 = *(const float4*)(g_dbc + (size_t)t * 64);
    float4 d1 = *(const float4*)(g_dbc + (size_t)t * 64 + 4);
    float u[8] = {d0.x, d0.y, d0.z, d0.w, d1.x, d1.y, d1.z, d1.w};
    float4 acc = *(const float4*)(dtb + c4);
#pragma unroll
    for (int k = 0; k < 8; k++) {
        float4 w = *(const float4*)(dtw + k * DIc + c4);
        acc.x = fmaf(u[k], w.x, acc.x);
        acc.y = fmaf(u[k], w.y, acc.y);
        acc.z = fmaf(u[k], w.z, acc.z);
        acc.w = fmaf(u[k], w.w, acc.w);
    }
    acc.x = softplus_f(acc.x);
    acc.y = softplus_f(acc.y);
    acc.z = softplus_f(acc.z);
    acc.w = softplus_f(acc.w);
    *(float4*)(g_dt + (size_t)t * DIc + c4) = acc;
}

// ---------------- kernel 6: extract B, C from dbc -----------------------------
__global__ void k_bc() {
    int idx = blockIdx.x * blockDim.x + threadIdx.x;  // N*16
    int t = idx >> 4;
    int s = idx & 15;
    g_Bm[idx] = g_dbc[(size_t)t * 64 + 8 + s];
    g_Cm[idx] = g_dbc[(size_t)t * 64 + 24 + s];
}

// ---------------- kernel 7: scan pass 1 (local chunk scan from h=0) -----------
__global__ void k_scan1(const float* __restrict__ A_log) {
    int chunk = blockIdx.x;
    int c = threadIdx.x;  // 256 channels
    __shared__ float Bs[LC][DSc];
    int t0 = chunk * LC;
    for (int i = threadIdx.x; i < LC * DSc; i += blockDim.x)
        Bs[i / DSc][i % DSc] = g_Bm[(size_t)t0 * DSc + i];
    __syncthreads();
    float A2[DSc];
#pragma unroll
    for (int s = 0; s < DSc; s++) A2[s] = -__expf(A_log[c * DSc + s]) * LOG2E;
    float h[DSc];
#pragma unroll
    for (int s = 0; s < DSc; s++) h[s] = 0.0f;
    float sdt = 0.0f;
#pragma unroll 2
    for (int t = 0; t < LC; t++) {
        float d = g_dt[(size_t)(t0 + t) * DIc + c];
        float x = g_xc[(size_t)(t0 + t) * DIc + c];
        float dx = d * x;
        sdt += d;
#pragma unroll
        for (int s = 0; s < DSc; s++) {
            float a = ex2(d * A2[s]);
            h[s] = fmaf(a, h[s], dx * Bs[t][s]);
        }
    }
    size_t o = ((size_t)chunk * DIc + c) * DSc;
#pragma unroll
    for (int s = 0; s < DSc; s++) {
        g_He[o + s] = h[s];
        g_P[o + s] = ex2(sdt * A2[s]);
    }
}

// ---------------- kernel 8: cross-chunk combine (serial over 256 chunks) ------
__global__ void k_combine() {
    int idx = blockIdx.x * blockDim.x + threadIdx.x;  // DIc*DSc = 4096
    float h = 0.0f;
    for (int k = 0; k < NCH; k++) {
        size_t o = (size_t)k * DIc * DSc + idx;
        g_Hin[o] = h;
        h = fmaf(g_P[o], h, g_He[o]);
    }
}

// ---------------- kernel 9: scan pass 2 (seeded replay + gate) ----------------
__global__ void k_scan2(const float* __restrict__ A_log, const float* __restrict__ Dskip) {
    int chunk = blockIdx.x;
    int c = threadIdx.x;
    __shared__ float Bs[LC][DSc];
    __shared__ float Cs[LC][DSc];
    int t0 = chunk * LC;
    for (int i = threadIdx.x; i < LC * DSc; i += blockDim.x) {
        Bs[i / DSc][i % DSc] = g_Bm[(size_t)t0 * DSc + i];
        Cs[i / DSc][i % DSc] = g_Cm[(size_t)t0 * DSc + i];
    }
    __syncthreads();
    float A2[DSc];
#pragma unroll
    for (int s = 0; s < DSc; s++) A2[s] = -__expf(A_log[c * DSc + s]) * LOG2E;
    float h[DSc];
    size_t oh = ((size_t)chunk * DIc + c) * DSc;
#pragma unroll
    for (int s = 0; s < DSc; s++) h[s] = g_Hin[oh + s];
    float dsk = Dskip[c];
#pragma unroll 2
    for (int t = 0; t < LC; t++) {
        float d = g_dt[(size_t)(t0 + t) * DIc + c];
        float x = g_xc[(size_t)(t0 + t) * DIc + c];
        float z = g_xz[(size_t)(t0 + t) * 512 + DIc + c];
        float dx = d * x;
        float acc = 0.0f;
#pragma unroll
        for (int s = 0; s < DSc; s++) {
            float a = ex2(d * A2[s]);
            h[s] = fmaf(a, h[s], dx * Bs[t][s]);
            acc = fmaf(h[s], Cs[t][s], acc);
        }
        acc = fmaf(dsk, x, acc);
        g_y[(size_t)(t0 + t) * DIc + c] = acc * silu_f(z);
    }
}

// ---------------- kernel 11: inv_perm gather + LayerNorm ----------------------
__global__ void k_ln(const int* __restrict__ inv_perm, const float* __restrict__ ln_w,
                     const float* __restrict__ ln_b, float* __restrict__ out) {
    int i = blockIdx.x;
    int d = threadIdx.x;  // 128
    int j = inv_perm[i];
    float v = g_x2[(size_t)j * DD + d];
    float s1 = v, s2 = v * v;
#pragma unroll
    for (int o = 16; o > 0; o >>= 1) {
        s1 += __shfl_xor_sync(0xffffffffu, s1, o);
        s2 += __shfl_xor_sync(0xffffffffu, s2, o);
    }
    __shared__ float rA[4], rB[4];
    if ((d & 31) == 0) { rA[d >> 5] = s1; rB[d >> 5] = s2; }
    __syncthreads();
    float mu = (rA[0] + rA[1] + rA[2] + rA[3]) * (1.0f / 128.0f);
    float e2 = (rB[0] + rB[1] + rB[2] + rB[3]) * (1.0f / 128.0f);
    float var = e2 - mu * mu;
    out[(size_t)i * DD + d] = (v - mu) * rsqrtf(var + EPSF) * ln_w[d] + ln_b[d];
}

// ---------------- host ---------------------------------------------------------
extern "C" void kernel_launch(void* const* d_in, const int* in_sizes, int n_in,
                              void* d_out, int out_size) {
    const float *vf, *pos_w, *pos_b, *rms_w, *in_proj_w, *conv_w, *conv_b, *x_proj_w;
    const float *dt_w, *dt_b, *A_log, *Dskip, *out_proj_w, *ln_w, *ln_b;
    const int *coords, *perm, *inv_perm;

    if (in_sizes[1] == NN * 4) {
        // setup_inputs() dict order
        vf = (const float*)d_in[0];
        coords = (const int*)d_in[1];
        perm = (const int*)d_in[2];
        inv_perm = (const int*)d_in[3];
        pos_w = (const float*)d_in[4];
        pos_b = (const float*)d_in[5];
        rms_w = (const float*)d_in[6];
        in_proj_w = (const float*)d_in[7];
        conv_w = (const float*)d_in[8];
        conv_b = (const float*)d_in[9];
        x_proj_w = (const float*)d_in[10];
        dt_w = (const float*)d_in[11];
        dt_b = (const float*)d_in[12];
        A_log = (const float*)d_in[13];
        Dskip = (const float*)d_in[14];
        out_proj_w = (const float*)d_in[15];
        ln_w = (const float*)d_in[16];
        ln_b = (const float*)d_in[17];
    } else {
        // reference() signature order
        vf = (const float*)d_in[0];
        pos_w = (const float*)d_in[1];
        pos_b = (const float*)d_in[2];
        rms_w = (const float*)d_in[3];
        in_proj_w = (const float*)d_in[4];
        conv_w = (const float*)d_in[5];
        conv_b = (const float*)d_in[6];
        x_proj_w = (const float*)d_in[7];
        dt_w = (const float*)d_in[8];
        dt_b = (const float*)d_in[9];
        A_log = (const float*)d_in[10];
        Dskip = (const float*)d_in[11];
        out_proj_w = (const float*)d_in[12];
        ln_w = (const float*)d_in[13];
        ln_b = (const float*)d_in[14];
        coords = (const int*)d_in[15];
        perm = (const int*)d_in[16];
        inv_perm = (const int*)d_in[17];
    }

    void *p_rms, *p_xz, *p_xc, *p_dbc, *p_xw64, *p_y, *p_x2, *p_resid;
    cudaGetSymbolAddress(&p_rms, g_rms);
    cudaGetSymbolAddress(&p_xz, g_xz);
    cudaGetSymbolAddress(&p_xc, g_xc);
    cudaGetSymbolAddress(&p_dbc, g_dbc);
    cudaGetSymbolAddress(&p_xw64, g_xw64);
    cudaGetSymbolAddress(&p_y, g_y);
    cudaGetSymbolAddress(&p_x2, g_x2);
    cudaGetSymbolAddress(&p_resid, g_resid);

    // 0. pad x_proj weights
    k_wpad<<<(DIc * 64 + 255) / 256, 256>>>(x_proj_w);
    // 1. pos-encode + gather + rms
    k_pre<<<NN, 128>>>(vf, coords, perm, pos_w, pos_b, rms_w);
    // 2. in_proj: xz[N,512] = rms[N,128] @ W[128,512]
    sgemm<128, 64, 16, 8, 4, false><<<dim3(NN / 128, 512 / 64), 256>>>(
        (const float*)p_rms, in_proj_w, nullptr, (float*)p_xz, 512, 128);
    // 3. causal conv + silu
    k_conv<<<NN * DIc / 256, 256>>>(conv_w, conv_b);
    // 4. dbc[N,64] = xc[N,256] @ xw64[256,64]
    sgemm<128, 64, 16, 8, 4, false><<<dim3(NN / 128, 1), 256>>>(
        (const float*)p_xc, (const float*)p_xw64, nullptr, (float*)p_dbc, 64, 256);
    // 5. dt
    k_dt<<<NN * 64 / 256, 256>>>(dt_w, dt_b);
    // 6. B, C
    k_bc<<<NN * DSc / 256, 256>>>();
    // 7-9. chunked scan
    k_scan1<<<NCH, DIc>>>(A_log);
    k_combine<<<DIc * DSc / 256, 256>>>();
    k_scan2<<<NCH, DIc>>>(A_log, Dskip);
    // 10. out_proj + residual
    sgemm<128, 64, 16, 8, 4, true><<<dim3(NN / 128, DD / 64), 256>>>(
        (const float*)p_y, out_proj_w, (const float*)p_resid, (float*)p_x2, DD, DIc);
    // 11. inv_perm + LayerNorm
    k_ln<<<NN, 128>>>(inv_perm, ln_w, ln_b, (float*)d_out);
    (void)n_in;
    (void)out_size;
    (void)in_sizes;
}

// round 3
// speedup vs baseline: 1.0681x; 1.0681x over previous
#include <cuda_runtime.h>
#include <cstdint>

#define NN 32768
#define DD 128
#define DIc 256
#define DSc 16
#define LC 128
#define NCH (NN / LC)
#define EPSF 1e-5f
#define LOG2E 1.4426950408889634f

// ---------------- scratch (device globals; no allocation allowed) -------------
__device__ float g_resid[NN * DD];
__device__ float g_rms[NN * DD];
__device__ float g_xz[NN * 2 * DIc];
__device__ float g_xc[NN * DIc];
__device__ float g_dbc[NN * 64];
__device__ float g_dt[NN * DIc];
__device__ float g_Bm[NN * DSc];
__device__ float g_Cm[NN * DSc];
__device__ float g_P[NCH * DIc * DSc];
__device__ float g_He[NCH * DIc * DSc];
__device__ float g_Hin[NCH * DIc * DSc];
__device__ float g_y[NN * DIc];
__device__ float g_x2[NN * DD];
__device__ float g_xw64[DIc * 64];

// ---------------- helpers -----------------------------------------------------
__device__ __forceinline__ float ex2(float x) {
    float y;
    asm("ex2.approx.ftz.f32 %0, %1;" : "=f"(y) : "f"(x));
    return y;
}
__device__ __forceinline__ float fexp(float x) { return ex2(x * LOG2E); }
__device__ __forceinline__ float silu_f(float x) { return x / (1.0f + fexp(-x)); }
__device__ __forceinline__ float softplus_f(float v) {
    if (v > 20.0f) return v;
    return log1pf(expf(v));
}
__device__ __forceinline__ uint32_t tf32_of(float f) {
    uint32_t u;
    asm("cvt.rna.tf32.f32 %0, %1;" : "=r"(u) : "f"(f));
    return u;
}

// ---------------- kernel 0: pad x_proj weights to 64 cols ---------------------
__global__ void k_wpad(const float* __restrict__ xw) {
    int idx = blockIdx.x * blockDim.x + threadIdx.x;
    if (idx < DIc * 64) {
        int k = idx >> 6, j = idx & 63;
        g_xw64[idx] = (j < 40) ? xw[k * 40 + j] : 0.0f;
    }
}

// ---------------- kernel 1: pos-encode + gather(perm) + RMSNorm ---------------
__global__ void k_pre(const float* __restrict__ vf, const int* __restrict__ coords,
                      const int* __restrict__ perm, const float* __restrict__ pos_w,
                      const float* __restrict__ pos_b, const float* __restrict__ rms_w) {
    int i = blockIdx.x;
    int d = threadIdx.x;  // 128
    int j = perm[i];
    int cz = coords[j * 4 + 1];
    int cy = coords[j * 4 + 2];
    int cx = coords[j * 4 + 3];
    const float dnm = 1.0f / 43.0f;
    const float t12 = 1.0f / 12.0f;
    float pf[9];
    pf[0] = (float)cz * (1.0f / 16.0f);
    pf[1] = (float)(cy / 12) * dnm;
    pf[2] = (float)(cx / 12) * dnm;
    pf[3] = (float)(cy % 12) * t12;
    pf[4] = (float)(cx % 12) * t12;
    pf[5] = (float)((cy + 6) / 12) * dnm;
    pf[6] = (float)((cx + 6) / 12) * dnm;
    pf[7] = (float)((cy + 6) % 12) * t12;
    pf[8] = (float)((cx + 6) % 12) * t12;
    float pe = pos_b[d];
#pragma unroll
    for (int f = 0; f < 9; f++) pe = fmaf(pf[f], pos_w[f * DD + d], pe);
    float val = vf[(size_t)j * DD + d] + pe;
    g_resid[(size_t)i * DD + d] = val;

    float v2 = val * val;
#pragma unroll
    for (int o = 16; o > 0; o >>= 1) v2 += __shfl_xor_sync(0xffffffffu, v2, o);
    __shared__ float red[4];
    if ((d & 31) == 0) red[d >> 5] = v2;
    __syncthreads();
    float ms = (red[0] + red[1] + red[2] + red[3]) * (1.0f / 128.0f);
    g_rms[(size_t)i * DD + d] = val * rsqrtf(ms + EPSF) * rms_w[d];
}

// ---------------- tf32 tensor-core GEMM: C[M,Nc] = A[M,Kd] @ B[Kd,Nc] (+S) ----
// block 256 thr = 8 warps (4 x 2); BM=128 BN=64 BK=32; warp tile 32x32.
// Shared memory holds A/B in mma-fragment order: A frag read = 1 LDS.128,
// B frag read = 1 LDS.64, both conflict-free.
template <bool ADD>
__global__ void tgemm(const float* __restrict__ A, const float* __restrict__ B,
                      const float* __restrict__ S, float* __restrict__ C,
                      int Nc, int Kd) {
    constexpr int BM = 128, BN = 64, BK = 32;
    __shared__ uint32_t Af[(BM / 16) * (BK / 8) * 32 * 4];  // 4096
    __shared__ uint32_t Bf[(BN / 8) * (BK / 8) * 32 * 2];   // 2048
    int tid = threadIdx.x;
    int lane = tid & 31;
    int warp = tid >> 5;
    int wr = warp & 3;   // warp row (4)
    int wc = warp >> 2;  // warp col (2)
    long row0 = (long)blockIdx.x * BM;
    int col0 = blockIdx.y * BN;

    float acc[2][4][4];
#pragma unroll
    for (int m = 0; m < 2; m++)
#pragma unroll
        for (int n = 0; n < 4; n++)
#pragma unroll
            for (int r = 0; r < 4; r++) acc[m][n][r] = 0.0f;

    for (int k0 = 0; k0 < Kd; k0 += BK) {
        // ---- load A tile (128x32): 4 float4 per thread, scatter to frag order
        {
            int r = tid >> 1;
            int kbase = (tid & 1) * 16;
#pragma unroll
            for (int j = 0; j < 4; j++) {
                int k = kbase + j * 4;
                float4 f = *(const float4*)(A + (row0 + r) * Kd + k0 + k);
                float e[4] = {f.x, f.y, f.z, f.w};
#pragma unroll
                for (int i = 0; i < 4; i++) {
                    int kk = k + i;
                    int mt = r >> 4;
                    int ks = kk >> 3;
                    int lan = ((r & 7) << 2) | (kk & 3);
                    int reg = ((kk >> 2) & 1) * 2 + ((r >> 3) & 1);
                    Af[(((mt << 2) + ks) * 32 + lan) * 4 + reg] = tf32_of(e[i]);
                }
            }
        }
        // ---- load B tile (32x64): 2 float4 per thread
        {
            int r = tid >> 3;
            int nbase = (tid & 7) * 8;
#pragma unroll
            for (int j = 0; j < 2; j++) {
                int n = nbase + j * 4;
                float4 f = *(const float4*)(B + (long)(k0 + r) * Nc + col0 + n);
                float e[4] = {f.x, f.y, f.z, f.w};
#pragma unroll
                for (int i = 0; i < 4; i++) {
                    int nn = n + i;
                    int nt = nn >> 3;
                    int ks = r >> 3;
                    int lan = ((nn & 7) << 2) | (r & 3);
                    int reg = (r >> 2) & 1;
                    Bf[(((nt << 2) + ks) * 32 + lan) * 2 + reg] = tf32_of(e[i]);
                }
            }
        }
        __syncthreads();
#pragma unroll
        for (int ks = 0; ks < 4; ks++) {
            uint32_t a[2][4];
            uint32_t b[4][2];
#pragma unroll
            for (int mt = 0; mt < 2; mt++) {
                const uint32_t* p = &Af[((((wr * 2 + mt) << 2) + ks) * 32 + lane) * 4];
                uint4 v = *(const uint4*)p;
                a[mt][0] = v.x; a[mt][1] = v.y; a[mt][2] = v.z; a[mt][3] = v.w;
            }
#pragma unroll
            for (int nt = 0; nt < 4; nt++) {
                const uint32_t* p = &Bf[((((wc * 4 + nt) << 2) + ks) * 32 + lane) * 2];
                uint2 v = *(const uint2*)p;
                b[nt][0] = v.x; b[nt][1] = v.y;
            }
#pragma unroll
            for (int mt = 0; mt < 2; mt++)
#pragma unroll
                for (int nt = 0; nt < 4; nt++) {
                    asm volatile(
                        "mma.sync.aligned.m16n8k8.row.col.f32.tf32.tf32.f32 "
                        "{%0,%1,%2,%3}, {%4,%5,%6,%7}, {%8,%9}, {%0,%1,%2,%3};"
                        : "+f"(acc[mt][nt][0]), "+f"(acc[mt][nt][1]),
                          "+f"(acc[mt][nt][2]), "+f"(acc[mt][nt][3])
                        : "r"(a[mt][0]), "r"(a[mt][1]), "r"(a[mt][2]), "r"(a[mt][3]),
                          "r"(b[nt][0]), "r"(b[nt][1]));
                }
        }
        __syncthreads();
    }

    // ---- epilogue
    int g = lane >> 2;
    int tg = lane & 3;
#pragma unroll
    for (int mt = 0; mt < 2; mt++) {
#pragma unroll
        for (int nt = 0; nt < 4; nt++) {
            long r0 = row0 + wr * 32 + mt * 16 + g;
            int c = col0 + wc * 32 + nt * 8 + tg * 2;
            float2 v0 = make_float2(acc[mt][nt][0], acc[mt][nt][1]);
            float2 v1 = make_float2(acc[mt][nt][2], acc[mt][nt][3]);
            if (ADD) {
                float2 s0 = *(const float2*)(S + r0 * Nc + c);
                float2 s1 = *(const float2*)(S + (r0 + 8) * Nc + c);
                v0.x += s0.x; v0.y += s0.y;
                v1.x += s1.x; v1.y += s1.y;
            }
            *(float2*)(C + r0 * Nc + c) = v0;
            *(float2*)(C + (r0 + 8) * Nc + c) = v1;
        }
    }
}

// ---------------- kernel 3: causal conv (K=4) + bias + silu -------------------
// each thread: one channel, 8 consecutive timesteps (reads 11 rows / 8 outputs)
__global__ void k_conv(const float* __restrict__ conv_w, const float* __restrict__ conv_b) {
    int idx = blockIdx.x * blockDim.x + threadIdx.x;  // (NN/8)*256
    int tb = idx >> 8;
    int c = idx & 255;
    int t0 = tb * 8;
    float w0 = conv_w[c * 4 + 0], w1 = conv_w[c * 4 + 1];
    float w2 = conv_w[c * 4 + 2], w3 = conv_w[c * 4 + 3];
    float bias = conv_b[c];
    float v[11];
#pragma unroll
    for (int i = 0; i < 11; i++) {
        int t = t0 - 3 + i;
        v[i] = (t >= 0) ? g_xz[(size_t)t * 512 + c] : 0.0f;
    }
#pragma unroll
    for (int j = 0; j < 8; j++) {
        float s = bias;
        s = fmaf(w0, v[j], s);
        s = fmaf(w1, v[j + 1], s);
        s = fmaf(w2, v[j + 2], s);
        s = fmaf(w3, v[j + 3], s);
        g_xc[(size_t)(t0 + j) * DIc + c] = silu_f(s);
    }
}

// ---------------- kernel 5: dt = softplus(dbc[:, :8] @ dt_w + dt_b) -----------
__global__ void k_dt(const float* __restrict__ dtw, const float* __restrict__ dtb) {
    int idx = blockIdx.x * blockDim.x + threadIdx.x;  // N*64
    int t = idx >> 6;
    int c4 = (idx & 63) * 4;
    float4 d0 = *(const float4*)(g_dbc + (size_t)t * 64);
    float4 d1 = *(const float4*)(g_dbc + (size_t)t * 64 + 4);
    float u[8] = {d0.x, d0.y, d0.z, d0.w, d1.x, d1.y, d1.z, d1.w};
    float4 acc = *(const float4*)(dtb + c4);
#pragma unroll
    for (int k = 0; k < 8; k++) {
        float4 w = *(const float4*)(dtw + k * DIc + c4);
        acc.x = fmaf(u[k], w.x, acc.x);
        acc.y = fmaf(u[k], w.y, acc.y);
        acc.z = fmaf(u[k], w.z, acc.z);
        acc.w = fmaf(u[k], w.w, acc.w);
    }
    acc.x = softplus_f(acc.x);
    acc.y = softplus_f(acc.y);
    acc.z = softplus_f(acc.z);
    acc.w = softplus_f(acc.w);
    *(float4*)(g_dt + (size_t)t * DIc + c4) = acc;
}

// ---------------- kernel 6: extract B, C from dbc -----------------------------
__global__ void k_bc() {
    int idx = blockIdx.x * blockDim.x + threadIdx.x;  // N*16
    int t = idx >> 4;
    int s = idx & 15;
    g_Bm[idx] = g_dbc[(size_t)t * 64 + 8 + s];
    g_Cm[idx] = g_dbc[(size_t)t * 64 + 24 + s];
}

// ---------------- kernel 7: scan pass 1 (local chunk scan from h=0) -----------
__global__ void k_scan1(const float* __restrict__ A_log) {
    int chunk = blockIdx.x;
    int c = threadIdx.x;
    __shared__ float Bs[LC][DSc];
    int t0 = chunk * LC;
    for (int i = threadIdx.x; i < LC * DSc; i += blockDim.x)
        Bs[i / DSc][i % DSc] = g_Bm[(size_t)t0 * DSc + i];
    __syncthreads();
    float A2[DSc];
#pragma unroll
    for (int s = 0; s < DSc; s++) A2[s] = -__expf(A_log[c * DSc + s]) * LOG2E;
    float h[DSc];
#pragma unroll
    for (int s = 0; s < DSc; s++) h[s] = 0.0f;
    float sdt = 0.0f;
#pragma unroll 2
    for (int t = 0; t < LC; t++) {
        float d = g_dt[(size_t)(t0 + t) * DIc + c];
        float x = g_xc[(size_t)(t0 + t) * DIc + c];
        float dx = d * x;
        sdt += d;
#pragma unroll
        for (int s = 0; s < DSc; s++) {
            float a = ex2(d * A2[s]);
            h[s] = fmaf(a, h[s], dx * Bs[t][s]);
        }
    }
    size_t o = ((size_t)chunk * DIc + c) * DSc;
#pragma unroll
    for (int s = 0; s < DSc; s++) {
        g_He[o + s] = h[s];
        g_P[o + s] = ex2(sdt * A2[s]);
    }
}

// ---------------- kernel 8: cross-chunk combine -------------------------------
__global__ void k_combine() {
    int idx = blockIdx.x * blockDim.x + threadIdx.x;  // 4096
    float h = 0.0f;
    for (int k = 0; k < NCH; k++) {
        size_t o = (size_t)k * DIc * DSc + idx;
        g_Hin[o] = h;
        h = fmaf(g_P[o], h, g_He[o]);
    }
}

// ---------------- kernel 9: scan pass 2 (seeded replay + gate) ----------------
__global__ void k_scan2(const float* __restrict__ A_log, const float* __restrict__ Dskip) {
    int chunk = blockIdx.x;
    int c = threadIdx.x;
    __shared__ float Bs[LC][DSc];
    __shared__ float Cs[LC][DSc];
    int t0 = chunk * LC;
    for (int i = threadIdx.x; i < LC * DSc; i += blockDim.x) {
        Bs[i / DSc][i % DSc] = g_Bm[(size_t)t0 * DSc + i];
        Cs[i / DSc][i % DSc] = g_Cm[(size_t)t0 * DSc + i];
    }
    __syncthreads();
    float A2[DSc];
#pragma unroll
    for (int s = 0; s < DSc; s++) A2[s] = -__expf(A_log[c * DSc + s]) * LOG2E;
    float h[DSc];
    size_t oh = ((size_t)chunk * DIc + c) * DSc;
#pragma unroll
    for (int s = 0; s < DSc; s++) h[s] = g_Hin[oh + s];
    float dsk = Dskip[c];
#pragma unroll 2
    for (int t = 0; t < LC; t++) {
        float d = g_dt[(size_t)(t0 + t) * DIc + c];
        float x = g_xc[(size_t)(t0 + t) * DIc + c];
        float z = g_xz[(size_t)(t0 + t) * 512 + DIc + c];
        float dx = d * x;
        float acc = 0.0f;
#pragma unroll
        for (int s = 0; s < DSc; s++) {
            float a = ex2(d * A2[s]);
            h[s] = fmaf(a, h[s], dx * Bs[t][s]);
            acc = fmaf(h[s], Cs[t][s], acc);
        }
        acc = fmaf(dsk, x, acc);
        g_y[(size_t)(t0 + t) * DIc + c] = acc * silu_f(z);
    }
}

// ---------------- kernel 11: inv_perm gather + LayerNorm ----------------------
__global__ void k_ln(const int* __restrict__ inv_perm, const float* __restrict__ ln_w,
                     const float* __restrict__ ln_b, float* __restrict__ out) {
    int i = blockIdx.x;
    int d = threadIdx.x;
    int j = inv_perm[i];
    float v = g_x2[(size_t)j * DD + d];
    float s1 = v, s2 = v * v;
#pragma unroll
    for (int o = 16; o > 0; o >>= 1) {
        s1 += __shfl_xor_sync(0xffffffffu, s1, o);
        s2 += __shfl_xor_sync(0xffffffffu, s2, o);
    }
    __shared__ float rA[4], rB[4];
    if ((d & 31) == 0) { rA[d >> 5] = s1; rB[d >> 5] = s2; }
    __syncthreads();
    float mu = (rA[0] + rA[1] + rA[2] + rA[3]) * (1.0f / 128.0f);
    float e2 = (rB[0] + rB[1] + rB[2] + rB[3]) * (1.0f / 128.0f);
    float var = e2 - mu * mu;
    out[(size_t)i * DD + d] = (v - mu) * rsqrtf(var + EPSF) * ln_w[d] + ln_b[d];
}

// ---------------- host ---------------------------------------------------------
extern "C" void kernel_launch(void* const* d_in, const int* in_sizes, int n_in,
                              void* d_out, int out_size) {
    const float *vf, *pos_w, *pos_b, *rms_w, *in_proj_w, *conv_w, *conv_b, *x_proj_w;
    const float *dt_w, *dt_b, *A_log, *Dskip, *out_proj_w, *ln_w, *ln_b;
    const int *coords, *perm, *inv_perm;

    if (in_sizes[1] == NN * 4) {
        vf = (const float*)d_in[0];
        coords = (const int*)d_in[1];
        perm = (const int*)d_in[2];
        inv_perm = (const int*)d_in[3];
        pos_w = (const float*)d_in[4];
        pos_b = (const float*)d_in[5];
        rms_w = (const float*)d_in[6];
        in_proj_w = (const float*)d_in[7];
        conv_w = (const float*)d_in[8];
        conv_b = (const float*)d_in[9];
        x_proj_w = (const float*)d_in[10];
        dt_w = (const float*)d_in[11];
        dt_b = (const float*)d_in[12];
        A_log = (const float*)d_in[13];
        Dskip = (const float*)d_in[14];
        out_proj_w = (const float*)d_in[15];
        ln_w = (const float*)d_in[16];
        ln_b = (const float*)d_in[17];
    } else {
        vf = (const float*)d_in[0];
        pos_w = (const float*)d_in[1];
        pos_b = (const float*)d_in[2];
        rms_w = (const float*)d_in[3];
        in_proj_w = (const float*)d_in[4];
        conv_w = (const float*)d_in[5];
        conv_b = (const float*)d_in[6];
        x_proj_w = (const float*)d_in[7];
        dt_w = (const float*)d_in[8];
        dt_b = (const float*)d_in[9];
        A_log = (const float*)d_in[10];
        Dskip = (const float*)d_in[11];
        out_proj_w = (const float*)d_in[12];
        ln_w = (const float*)d_in[13];
        ln_b = (const float*)d_in[14];
        coords = (const int*)d_in[15];
        perm = (const int*)d_in[16];
        inv_perm = (const int*)d_in[17];
    }

    void *p_rms, *p_xz, *p_xc, *p_dbc, *p_xw64, *p_y, *p_x2, *p_resid;
    cudaGetSymbolAddress(&p_rms, g_rms);
    cudaGetSymbolAddress(&p_xz, g_xz);
    cudaGetSymbolAddress(&p_xc, g_xc);
    cudaGetSymbolAddress(&p_dbc, g_dbc);
    cudaGetSymbolAddress(&p_xw64, g_xw64);
    cudaGetSymbolAddress(&p_y, g_y);
    cudaGetSymbolAddress(&p_x2, g_x2);
    cudaGetSymbolAddress(&p_resid, g_resid);

    k_wpad<<<(DIc * 64 + 255) / 256, 256>>>(x_proj_w);
    k_pre<<<NN, 128>>>(vf, coords, perm, pos_w, pos_b, rms_w);
    // in_proj: xz[N,512] = rms[N,128] @ W[128,512]
    tgemm<false><<<dim3(NN / 128, 512 / 64), 256>>>(
        (const float*)p_rms, in_proj_w, nullptr, (float*)p_xz, 512, 128);
    k_conv<<<(NN / 8) * 256 / 256, 256>>>(conv_w, conv_b);
    // x_proj: dbc[N,64] = xc[N,256] @ xw64[256,64]
    tgemm<false><<<dim3(NN / 128, 1), 256>>>(
        (const float*)p_xc, (const float*)p_xw64, nullptr, (float*)p_dbc, 64, 256);
    k_dt<<<NN * 64 / 256, 256>>>(dt_w, dt_b);
    k_bc<<<NN * DSc / 256, 256>>>();
    k_scan1<<<NCH, DIc>>>(A_log);
    k_combine<<<DIc * DSc / 256, 256>>>();
    k_scan2<<<NCH, DIc>>>(A_log, Dskip);
    // out_proj + residual
    tgemm<true><<<dim3(NN / 128, DD / 64), 256>>>(
        (const float*)p_y, out_proj_w, (const float*)p_resid, (float*)p_x2, DD, DIc);
    k_ln<<<NN, 128>>>(inv_perm, ln_w, ln_b, (float*)d_out);
    (void)n_in;
    (void)out_size;
    (void)in_sizes;
}

// round 5
// speedup vs baseline: 1.3991x; 1.3099x over previous
#include <cuda_runtime.h>
#include <cuda_bf16.h>
#include <cstdint>

#define NN 32768
#define DD 128
#define DIc 256
#define DSc 16
#define LC 128
#define NCH (NN / LC)
#define EPSF 1e-5f
#define LOG2E 1.4426950408889634f

// ---------------- scratch (device globals; no allocation allowed) -------------
__device__ float g_resid[NN * DD];
__device__ float g_rms[NN * DD];
__device__ float g_xz[NN * 2 * DIc];
__device__ float g_xc[NN * DIc];
__device__ float g_dbc[NN * 64];
__device__ float g_dt[NN * DIc];
__device__ float g_Bm[NN * DSc];
__device__ float g_Cm[NN * DSc];
__device__ float g_P[NCH * DIc * DSc];
__device__ float g_He[NCH * DIc * DSc];
__device__ float g_Hin[NCH * DIc * DSc];
__device__ float g_y[NN * DIc];
__device__ float g_x2[NN * DD];
__device__ float g_xw64[DIc * 64];

// ---------------- helpers -----------------------------------------------------
__device__ __forceinline__ float ex2(float x) {
    float y;
    asm("ex2.approx.ftz.f32 %0, %1;" : "=f"(y) : "f"(x));
    return y;
}
__device__ __forceinline__ float fexp(float x) { return ex2(x * LOG2E); }
__device__ __forceinline__ float silu_f(float x) { return x / (1.0f + fexp(-x)); }
__device__ __forceinline__ float softplus_f(float v) {
    if (v > 20.0f) return v;
    return log1pf(expf(v));
}
__device__ __forceinline__ uint32_t pk(float x, float y) {
    __nv_bfloat162 h = __float22bfloat162_rn(make_float2(x, y));
    return *(uint32_t*)&h;
}
__device__ __forceinline__ void ldsm4(uint32_t& r0, uint32_t& r1, uint32_t& r2, uint32_t& r3,
                                      uint32_t a) {
    asm volatile("ldmatrix.sync.aligned.m8n8.x4.shared.b16 {%0,%1,%2,%3},[%4];"
                 : "=r"(r0), "=r"(r1), "=r"(r2), "=r"(r3)
                 : "r"(a));
}
__device__ __forceinline__ void ldsm4t(uint32_t& r0, uint32_t& r1, uint32_t& r2, uint32_t& r3,
                                       uint32_t a) {
    asm volatile("ldmatrix.sync.aligned.m8n8.x4.trans.shared.b16 {%0,%1,%2,%3},[%4];"
                 : "=r"(r0), "=r"(r1), "=r"(r2), "=r"(r3)
                 : "r"(a));
}
__device__ __forceinline__ void mma_bf16(float* c, const uint32_t* a, const uint32_t* b) {
    asm volatile(
        "mma.sync.aligned.m16n8k16.row.col.f32.bf16.bf16.f32 "
        "{%0,%1,%2,%3},{%4,%5,%6,%7},{%8,%9},{%0,%1,%2,%3};"
        : "+f"(c[0]), "+f"(c[1]), "+f"(c[2]), "+f"(c[3])
        : "r"(a[0]), "r"(a[1]), "r"(a[2]), "r"(a[3]), "r"(b[0]), "r"(b[1]));
}

// ---------------- kernel 0: pad x_proj weights to 64 cols ---------------------
__global__ void k_wpad(const float* __restrict__ xw) {
    int idx = blockIdx.x * blockDim.x + threadIdx.x;
    if (idx < DIc * 64) {
        int k = idx >> 6, j = idx & 63;
        g_xw64[idx] = (j < 40) ? xw[k * 40 + j] : 0.0f;
    }
}

// ---------------- kernel 1: pos-encode + gather(perm) + RMSNorm ---------------
__global__ void k_pre(const float* __restrict__ vf, const int* __restrict__ coords,
                      const int* __restrict__ perm, const float* __restrict__ pos_w,
                      const float* __restrict__ pos_b, const float* __restrict__ rms_w) {
    int i = blockIdx.x;
    int d = threadIdx.x;  // 128
    int j = perm[i];
    int cz = coords[j * 4 + 1];
    int cy = coords[j * 4 + 2];
    int cx = coords[j * 4 + 3];
    const float dnm = 1.0f / 43.0f;
    const float t12 = 1.0f / 12.0f;
    float pf[9];
    pf[0] = (float)cz * (1.0f / 16.0f);
    pf[1] = (float)(cy / 12) * dnm;
    pf[2] = (float)(cx / 12) * dnm;
    pf[3] = (float)(cy % 12) * t12;
    pf[4] = (float)(cx % 12) * t12;
    pf[5] = (float)((cy + 6) / 12) * dnm;
    pf[6] = (float)((cx + 6) / 12) * dnm;
    pf[7] = (float)((cy + 6) % 12) * t12;
    pf[8] = (float)((cx + 6) % 12) * t12;
    float pe = pos_b[d];
#pragma unroll
    for (int f = 0; f < 9; f++) pe = fmaf(pf[f], pos_w[f * DD + d], pe);
    float val = vf[(size_t)j * DD + d] + pe;
    g_resid[(size_t)i * DD + d] = val;

    float v2 = val * val;
#pragma unroll
    for (int o = 16; o > 0; o >>= 1) v2 += __shfl_xor_sync(0xffffffffu, v2, o);
    __shared__ float red[4];
    if ((d & 31) == 0) red[d >> 5] = v2;
    __syncthreads();
    float ms = (red[0] + red[1] + red[2] + red[3]) * (1.0f / 128.0f);
    g_rms[(size_t)i * DD + d] = val * rsqrtf(ms + EPSF) * rms_w[d];
}

// ---------------- bf16 tensor-core GEMM: C[M,Nc] = A[M,Kd]@B[Kd,Nc] (+S) ------
// 256 threads = 8 warps (4 x 2). BM = MT*64 (128 or 64), BN=64, BK=32.
// smem: A row-major bf16, 80B rows; B row-major bf16, 144B rows. ldmatrix frags.
template <int MT, bool ADD>
__global__ void bgemm(const float* __restrict__ A, const float* __restrict__ B,
                      const float* __restrict__ S, float* __restrict__ C,
                      int Nc, int Kd) {
    constexpr int BM = MT * 64;
    constexpr int BN = 64, BK = 32;
    constexpr int LDA = 80;   // bytes per A smem row (32 halves + pad)
    constexpr int LDB = 144;  // bytes per B smem row (64 halves + pad)
    __shared__ __align__(16) unsigned char As[BM * LDA];
    __shared__ __align__(16) unsigned char Bs[BK * LDB];
    int tid = threadIdx.x;
    int lane = tid & 31;
    int warp = tid >> 5;
    int wr = warp & 3;   // 4 warp rows
    int wc = warp >> 2;  // 2 warp cols
    long row0 = (long)blockIdx.x * BM;
    int col0 = blockIdx.y * BN;

    float acc[MT][4][4];
#pragma unroll
    for (int m = 0; m < MT; m++)
#pragma unroll
        for (int n = 0; n < 4; n++)
#pragma unroll
            for (int r = 0; r < 4; r++) acc[m][n][r] = 0.0f;

    uint32_t asb = (uint32_t)__cvta_generic_to_shared(As);
    uint32_t bsb = (uint32_t)__cvta_generic_to_shared(Bs);

    // precomputed ldmatrix lane addressing
    int a_row_in_tile = lane & 15;            // 0..15
    int a_colh = ((lane >> 4) << 3);          // 0 or 8 halves
    int b_krow = (lane & 7) + (((lane >> 3) & 1) << 3);  // 0..15
    int b_ncol = ((lane >> 4) << 3);          // 0 or 8

    for (int k0 = 0; k0 < Kd; k0 += BK) {
        // ---- A tile: BM x 32 halves; each thread it-loop: 8 floats -> 1 STS.128
#pragma unroll
        for (int it = 0; it < MT; it++) {
            int v = tid + it * 256;  // < BM*4
            int r = v >> 2;
            int c0 = (v & 3) * 8;
            const float4* p = (const float4*)(A + (row0 + r) * Kd + k0 + c0);
            float4 f0 = p[0], f1 = p[1];
            uint4 u;
            u.x = pk(f0.x, f0.y);
            u.y = pk(f0.z, f0.w);
            u.z = pk(f1.x, f1.y);
            u.w = pk(f1.z, f1.w);
            *(uint4*)(As + r * LDA + c0 * 2) = u;
        }
        // ---- B tile: 32 x 64 halves; each thread 8 floats -> 1 STS.128
        {
            int r = tid >> 3;
            int c0 = (tid & 7) * 8;
            const float4* p = (const float4*)(B + (long)(k0 + r) * Nc + col0 + c0);
            float4 f0 = p[0], f1 = p[1];
            uint4 u;
            u.x = pk(f0.x, f0.y);
            u.y = pk(f0.z, f0.w);
            u.z = pk(f1.x, f1.y);
            u.w = pk(f1.z, f1.w);
            *(uint4*)(Bs + r * LDB + c0 * 2) = u;
        }
        __syncthreads();
#pragma unroll
        for (int ks = 0; ks < 2; ks++) {
            int kh = ks * 16;
            uint32_t a[MT][4];
#pragma unroll
            for (int mt = 0; mt < MT; mt++) {
                int row = wr * (MT * 16) + mt * 16 + a_row_in_tile;
                uint32_t addr = asb + row * LDA + (kh + a_colh) * 2;
                ldsm4(a[mt][0], a[mt][1], a[mt][2], a[mt][3], addr);
            }
            uint32_t b[4][2];
#pragma unroll
            for (int np = 0; np < 2; np++) {
                int krow = kh + b_krow;
                int ncol = wc * 32 + np * 16 + b_ncol;
                uint32_t addr = bsb + krow * LDB + ncol * 2;
                uint32_t r0, r1, r2, r3;
                ldsm4t(r0, r1, r2, r3, addr);
                b[np * 2][0] = r0;
                b[np * 2][1] = r1;
                b[np * 2 + 1][0] = r2;
                b[np * 2 + 1][1] = r3;
            }
#pragma unroll
            for (int mt = 0; mt < MT; mt++)
#pragma unroll
                for (int nt = 0; nt < 4; nt++) mma_bf16(acc[mt][nt], a[mt], b[nt]);
        }
        __syncthreads();
    }

    // ---- epilogue
    int g = lane >> 2;
    int tg = lane & 3;
#pragma unroll
    for (int mt = 0; mt < MT; mt++) {
#pragma unroll
        for (int nt = 0; nt < 4; nt++) {
            long r0 = row0 + wr * (MT * 16) + mt * 16 + g;
            int c = col0 + wc * 32 + nt * 8 + tg * 2;
            float2 v0 = make_float2(acc[mt][nt][0], acc[mt][nt][1]);
            float2 v1 = make_float2(acc[mt][nt][2], acc[mt][nt][3]);
            if (ADD) {
                float2 s0 = *(const float2*)(S + r0 * Nc + c);
                float2 s1 = *(const float2*)(S + (r0 + 8) * Nc + c);
                v0.x += s0.x; v0.y += s0.y;
                v1.x += s1.x; v1.y += s1.y;
            }
            *(float2*)(C + r0 * Nc + c) = v0;
            *(float2*)(C + (r0 + 8) * Nc + c) = v1;
        }
    }
}

// ---------------- kernel 3: causal conv (K=4) + bias + silu -------------------
__global__ void k_conv(const float* __restrict__ conv_w, const float* __restrict__ conv_b) {
    int idx = blockIdx.x * blockDim.x + threadIdx.x;
    int tb = idx >> 8;
    int c = idx & 255;
    int t0 = tb * 8;
    float w0 = conv_w[c * 4 + 0], w1 = conv_w[c * 4 + 1];
    float w2 = conv_w[c * 4 + 2], w3 = conv_w[c * 4 + 3];
    float bias = conv_b[c];
    float v[11];
#pragma unroll
    for (int i = 0; i < 11; i++) {
        int t = t0 - 3 + i;
        v[i] = (t >= 0) ? g_xz[(size_t)t * 512 + c] : 0.0f;
    }
#pragma unroll
    for (int j = 0; j < 8; j++) {
        float s = bias;
        s = fmaf(w0, v[j], s);
        s = fmaf(w1, v[j + 1], s);
        s = fmaf(w2, v[j + 2], s);
        s = fmaf(w3, v[j + 3], s);
        g_xc[(size_t)(t0 + j) * DIc + c] = silu_f(s);
    }
}

// ---------------- kernel 5: dt = softplus(dbc[:, :8] @ dt_w + dt_b) -----------
__global__ void k_dt(const float* __restrict__ dtw, const float* __restrict__ dtb) {
    int idx = blockIdx.x * blockDim.x + threadIdx.x;
    int t = idx >> 6;
    int c4 = (idx & 63) * 4;
    float4 d0 = *(const float4*)(g_dbc + (size_t)t * 64);
    float4 d1 = *(const float4*)(g_dbc + (size_t)t * 64 + 4);
    float u[8] = {d0.x, d0.y, d0.z, d0.w, d1.x, d1.y, d1.z, d1.w};
    float4 acc = *(const float4*)(dtb + c4);
#pragma unroll
    for (int k = 0; k < 8; k++) {
        float4 w = *(const float4*)(dtw + k * DIc + c4);
        acc.x = fmaf(u[k], w.x, acc.x);
        acc.y = fmaf(u[k], w.y, acc.y);
        acc.z = fmaf(u[k], w.z, acc.z);
        acc.w = fmaf(u[k], w.w, acc.w);
    }
    acc.x = softplus_f(acc.x);
    acc.y = softplus_f(acc.y);
    acc.z = softplus_f(acc.z);
    acc.w = softplus_f(acc.w);
    *(float4*)(g_dt + (size_t)t * DIc + c4) = acc;
}

// ---------------- kernel 6: extract B, C from dbc -----------------------------
__global__ void k_bc() {
    int idx = blockIdx.x * blockDim.x + threadIdx.x;
    int t = idx >> 4;
    int s = idx & 15;
    g_Bm[idx] = g_dbc[(size_t)t * 64 + 8 + s];
    g_Cm[idx] = g_dbc[(size_t)t * 64 + 24 + s];
}

// ---------------- kernel 7: scan pass 1 ---------------------------------------
__global__ void k_scan1(const float* __restrict__ A_log) {
    int chunk = blockIdx.x;
    int c = threadIdx.x;
    __shared__ float Bs[LC][DSc];
    int t0 = chunk * LC;
    for (int i = threadIdx.x; i < LC * DSc; i += blockDim.x)
        Bs[i / DSc][i % DSc] = g_Bm[(size_t)t0 * DSc + i];
    __syncthreads();
    float A2[DSc];
#pragma unroll
    for (int s = 0; s < DSc; s++) A2[s] = -__expf(A_log[c * DSc + s]) * LOG2E;
    float h[DSc];
#pragma unroll
    for (int s = 0; s < DSc; s++) h[s] = 0.0f;
    float sdt = 0.0f;
#pragma unroll 2
    for (int t = 0; t < LC; t++) {
        float d = g_dt[(size_t)(t0 + t) * DIc + c];
        float x = g_xc[(size_t)(t0 + t) * DIc + c];
        float dx = d * x;
        sdt += d;
#pragma unroll
        for (int s = 0; s < DSc; s++) {
            float a = ex2(d * A2[s]);
            h[s] = fmaf(a, h[s], dx * Bs[t][s]);
        }
    }
    size_t o = ((size_t)chunk * DIc + c) * DSc;
#pragma unroll
    for (int s = 0; s < DSc; s++) {
        g_He[o + s] = h[s];
        g_P[o + s] = ex2(sdt * A2[s]);
    }
}

// ---------------- kernel 8: cross-chunk combine -------------------------------
__global__ void k_combine() {
    int idx = blockIdx.x * blockDim.x + threadIdx.x;
    float h = 0.0f;
    for (int k = 0; k < NCH; k++) {
        size_t o = (size_t)k * DIc * DSc + idx;
        g_Hin[o] = h;
        h = fmaf(g_P[o], h, g_He[o]);
    }
}

// ---------------- kernel 9: scan pass 2 (seeded replay + gate) ----------------
__global__ void k_scan2(const float* __restrict__ A_log, const float* __restrict__ Dskip) {
    int chunk = blockIdx.x;
    int c = threadIdx.x;
    __shared__ float Bs[LC][DSc];
    __shared__ float Cs[LC][DSc];
    int t0 = chunk * LC;
    for (int i = threadIdx.x; i < LC * DSc; i += blockDim.x) {
        Bs[i / DSc][i % DSc] = g_Bm[(size_t)t0 * DSc + i];
        Cs[i / DSc][i % DSc] = g_Cm[(size_t)t0 * DSc + i];
    }
    __syncthreads();
    float A2[DSc];
#pragma unroll
    for (int s = 0; s < DSc; s++) A2[s] = -__expf(A_log[c * DSc + s]) * LOG2E;
    float h[DSc];
    size_t oh = ((size_t)chunk * DIc + c) * DSc;
#pragma unroll
    for (int s = 0; s < DSc; s++) h[s] = g_Hin[oh + s];
    float dsk = Dskip[c];
#pragma unroll 2
    for (int t = 0; t < LC; t++) {
        float d = g_dt[(size_t)(t0 + t) * DIc + c];
        float x = g_xc[(size_t)(t0 + t) * DIc + c];
        float z = g_xz[(size_t)(t0 + t) * 512 + DIc + c];
        float dx = d * x;
        float acc = 0.0f;
#pragma unroll
        for (int s = 0; s < DSc; s++) {
            float a = ex2(d * A2[s]);
            h[s] = fmaf(a, h[s], dx * Bs[t][s]);
            acc = fmaf(h[s], Cs[t][s], acc);
        }
        acc = fmaf(dsk, x, acc);
        g_y[(size_t)(t0 + t) * DIc + c] = acc * silu_f(z);
    }
}

// ---------------- kernel 11: inv_perm gather + LayerNorm ----------------------
__global__ void k_ln(const int* __restrict__ inv_perm, const float* __restrict__ ln_w,
                     const float* __restrict__ ln_b, float* __restrict__ out) {
    int i = blockIdx.x;
    int d = threadIdx.x;
    int j = inv_perm[i];
    float v = g_x2[(size_t)j * DD + d];
    float s1 = v, s2 = v * v;
#pragma unroll
    for (int o = 16; o > 0; o >>= 1) {
        s1 += __shfl_xor_sync(0xffffffffu, s1, o);
        s2 += __shfl_xor_sync(0xffffffffu, s2, o);
    }
    __shared__ float rA[4], rB[4];
    if ((d & 31) == 0) { rA[d >> 5] = s1; rB[d >> 5] = s2; }
    __syncthreads();
    float mu = (rA[0] + rA[1] + rA[2] + rA[3]) * (1.0f / 128.0f);
    float e2 = (rB[0] + rB[1] + rB[2] + rB[3]) * (1.0f / 128.0f);
    float var = e2 - mu * mu;
    out[(size_t)i * DD + d] = (v - mu) * rsqrtf(var + EPSF) * ln_w[d] + ln_b[d];
}

// ---------------- host ---------------------------------------------------------
extern "C" void kernel_launch(void* const* d_in, const int* in_sizes, int n_in,
                              void* d_out, int out_size) {
    const float *vf, *pos_w, *pos_b, *rms_w, *in_proj_w, *conv_w, *conv_b, *x_proj_w;
    const float *dt_w, *dt_b, *A_log, *Dskip, *out_proj_w, *ln_w, *ln_b;
    const int *coords, *perm, *inv_perm;

    if (in_sizes[1] == NN * 4) {
        vf = (const float*)d_in[0];
        coords = (const int*)d_in[1];
        perm = (const int*)d_in[2];
        inv_perm = (const int*)d_in[3];
        pos_w = (const float*)d_in[4];
        pos_b = (const float*)d_in[5];
        rms_w = (const float*)d_in[6];
        in_proj_w = (const float*)d_in[7];
        conv_w = (const float*)d_in[8];
        conv_b = (const float*)d_in[9];
        x_proj_w = (const float*)d_in[10];
        dt_w = (const float*)d_in[11];
        dt_b = (const float*)d_in[12];
        A_log = (const float*)d_in[13];
        Dskip = (const float*)d_in[14];
        out_proj_w = (const float*)d_in[15];
        ln_w = (const float*)d_in[16];
        ln_b = (const float*)d_in[17];
    } else {
        vf = (const float*)d_in[0];
        pos_w = (const float*)d_in[1];
        pos_b = (const float*)d_in[2];
        rms_w = (const float*)d_in[3];
        in_proj_w = (const float*)d_in[4];
        conv_w = (const float*)d_in[5];
        conv_b = (const float*)d_in[6];
        x_proj_w = (const float*)d_in[7];
        dt_w = (const float*)d_in[8];
        dt_b = (const float*)d_in[9];
        A_log = (const float*)d_in[10];
        Dskip = (const float*)d_in[11];
        out_proj_w = (const float*)d_in[12];
        ln_w = (const float*)d_in[13];
        ln_b = (const float*)d_in[14];
        coords = (const int*)d_in[15];
        perm = (const int*)d_in[16];
        inv_perm = (const int*)d_in[17];
    }

    void *p_rms, *p_xz, *p_xc, *p_dbc, *p_xw64, *p_y, *p_x2, *p_resid;
    cudaGetSymbolAddress(&p_rms, g_rms);
    cudaGetSymbolAddress(&p_xz, g_xz);
    cudaGetSymbolAddress(&p_xc, g_xc);
    cudaGetSymbolAddress(&p_dbc, g_dbc);
    cudaGetSymbolAddress(&p_xw64, g_xw64);
    cudaGetSymbolAddress(&p_y, g_y);
    cudaGetSymbolAddress(&p_x2, g_x2);
    cudaGetSymbolAddress(&p_resid, g_resid);

    k_wpad<<<(DIc * 64 + 255) / 256, 256>>>(x_proj_w);
    k_pre<<<NN, 128>>>(vf, coords, perm, pos_w, pos_b, rms_w);
    // in_proj: xz[N,512] = rms[N,128] @ W[128,512]
    bgemm<2, false><<<dim3(NN / 128, 512 / 64), 256>>>(
        (const float*)p_rms, in_proj_w, nullptr, (float*)p_xz, 512, 128);
    k_conv<<<(NN / 8), 256>>>(conv_w, conv_b);
    // x_proj: dbc[N,64] = xc[N,256] @ xw64[256,64]  (BM=64 -> 512 blocks)
    bgemm<1, false><<<dim3(NN / 64, 1), 256>>>(
        (const float*)p_xc, (const float*)p_xw64, nullptr, (float*)p_dbc, 64, 256);
    k_dt<<<NN * 64 / 256, 256>>>(dt_w, dt_b);
    k_bc<<<NN * DSc / 256, 256>>>();
    k_scan1<<<NCH, DIc>>>(A_log);
    k_combine<<<DIc * DSc / 256, 256>>>();
    k_scan2<<<NCH, DIc>>>(A_log, Dskip);
    // out_proj + residual: x2[N,128] = y[N,256] @ W[256,128] + resid
    bgemm<2, true><<<dim3(NN / 128, DD / 64), 256>>>(
        (const float*)p_y, out_proj_w, (const float*)p_resid, (float*)p_x2, DD, DIc);
    k_ln<<<NN, 128>>>(inv_perm, ln_w, ln_b, (float*)d_out);
    (void)n_in;
    (void)out_size;
    (void)in_sizes;
}

// round 7
// speedup vs baseline: 1.4706x; 1.0511x over previous
#include <cuda_runtime.h>
#include <cuda_bf16.h>
#include <cstdint>

#define NN 32768
#define DD 128
#define DIc 256
#define DSc 16
#define LC 128
#define NCH (NN / LC)
#define EPSF 1e-5f
#define LOG2E 1.4426950408889634f

// ---------------- scratch (device globals; no allocation allowed) -------------
__device__ float g_resid[NN * DD];
__device__ __nv_bfloat16 g_rmsb[NN * DD];
__device__ float g_xz[NN * 2 * DIc];
__device__ float g_xc[NN * DIc];
__device__ __nv_bfloat16 g_xcb[NN * DIc];
__device__ float g_dbc[NN * 64];
__device__ float g_dt[NN * DIc];
__device__ float g_Bm[NN * DSc];
__device__ float g_Cm[NN * DSc];
__device__ float g_P[NCH * DIc * DSc];
__device__ float g_He[NCH * DIc * DSc];
__device__ float g_Hin[NCH * DIc * DSc];
__device__ __nv_bfloat16 g_yb[NN * DIc];
__device__ float g_x2[NN * DD];
__device__ __nv_bfloat16 g_w1b[DD * 512];
__device__ __nv_bfloat16 g_w2b[DIc * 64];
__device__ __nv_bfloat16 g_w3b[DIc * DD];

// ---------------- helpers -----------------------------------------------------
__device__ __forceinline__ float ex2(float x) {
    float y;
    asm("ex2.approx.ftz.f32 %0, %1;" : "=f"(y) : "f"(x));
    return y;
}
__device__ __forceinline__ float fexp(float x) { return ex2(x * LOG2E); }
__device__ __forceinline__ float silu_f(float x) { return x / (1.0f + fexp(-x)); }
__device__ __forceinline__ float softplus_f(float v) {
    if (v > 20.0f) return v;
    return log1pf(expf(v));
}
__device__ __forceinline__ void ldsm4(uint32_t& r0, uint32_t& r1, uint32_t& r2, uint32_t& r3,
                                      uint32_t a) {
    asm volatile("ldmatrix.sync.aligned.m8n8.x4.shared.b16 {%0,%1,%2,%3},[%4];"
                 : "=r"(r0), "=r"(r1), "=r"(r2), "=r"(r3)
                 : "r"(a));
}
__device__ __forceinline__ void ldsm4t(uint32_t& r0, uint32_t& r1, uint32_t& r2, uint32_t& r3,
                                       uint32_t a) {
    asm volatile("ldmatrix.sync.aligned.m8n8.x4.trans.shared.b16 {%0,%1,%2,%3},[%4];"
                 : "=r"(r0), "=r"(r1), "=r"(r2), "=r"(r3)
                 : "r"(a));
}
__device__ __forceinline__ void mma_bf16(float* c, const uint32_t* a, const uint32_t* b) {
    asm volatile(
        "mma.sync.aligned.m16n8k16.row.col.f32.bf16.bf16.f32 "
        "{%0,%1,%2,%3},{%4,%5,%6,%7},{%8,%9},{%0,%1,%2,%3};"
        : "+f"(c[0]), "+f"(c[1]), "+f"(c[2]), "+f"(c[3])
        : "r"(a[0]), "r"(a[1]), "r"(a[2]), "r"(a[3]), "r"(b[0]), "r"(b[1]));
}
__device__ __forceinline__ void cpa16(uint32_t s, const void* g) {
    asm volatile("cp.async.cg.shared.global [%0], [%1], 16;" ::"r"(s), "l"(g));
}
__device__ __forceinline__ void cp_commit() { asm volatile("cp.async.commit_group;"); }
template <int NG>
__device__ __forceinline__ void cp_wait() {
    asm volatile("cp.async.wait_group %0;" ::"n"(NG));
}
// r^(s+1) for s=0..15, log-depth
__device__ __forceinline__ void pow_chain(float r, float* a) {
    a[0] = r;
    a[1] = r * r;
    a[2] = a[1] * r;
    a[3] = a[1] * a[1];
    a[4] = a[3] * r;
    a[5] = a[2] * a[2];
    a[6] = a[5] * r;
    a[7] = a[3] * a[3];
    a[8] = a[7] * r;
    a[9] = a[4] * a[4];
    a[10] = a[9] * r;
    a[11] = a[5] * a[5];
    a[12] = a[11] * r;
    a[13] = a[6] * a[6];
    a[14] = a[13] * r;
    a[15] = a[7] * a[7];
}

// ---------------- kernel 0: convert weights to bf16 (+ pad x_proj) ------------
__global__ void k_wcvt(const float* __restrict__ w1, const float* __restrict__ xw,
                       const float* __restrict__ w3) {
    int idx = blockIdx.x * blockDim.x + threadIdx.x;  // 448*256 = 114688
    if (idx < DD * 512) {
        g_w1b[idx] = __float2bfloat16(w1[idx]);
    } else if (idx < DD * 512 + DIc * 64) {
        int i = idx - DD * 512;
        int k = i >> 6, j = i & 63;
        g_w2b[i] = __float2bfloat16(j < 40 ? xw[k * 40 + j] : 0.0f);
    } else {
        int i = idx - DD * 512 - DIc * 64;
        g_w3b[i] = __float2bfloat16(w3[i]);
    }
}

// ---------------- kernel 1: pos-encode + gather(perm) + RMSNorm ---------------
__global__ void k_pre(const float* __restrict__ vf, const int* __restrict__ coords,
                      const int* __restrict__ perm, const float* __restrict__ pos_w,
                      const float* __restrict__ pos_b, const float* __restrict__ rms_w) {
    int i = blockIdx.x;
    int d = threadIdx.x;  // 128
    int j = perm[i];
    int cz = coords[j * 4 + 1];
    int cy = coords[j * 4 + 2];
    int cx = coords[j * 4 + 3];
    const float dnm = 1.0f / 43.0f;
    const float t12 = 1.0f / 12.0f;
    float pf[9];
    pf[0] = (float)cz * (1.0f / 16.0f);
    pf[1] = (float)(cy / 12) * dnm;
    pf[2] = (float)(cx / 12) * dnm;
    pf[3] = (float)(cy % 12) * t12;
    pf[4] = (float)(cx % 12) * t12;
    pf[5] = (float)((cy + 6) / 12) * dnm;
    pf[6] = (float)((cx + 6) / 12) * dnm;
    pf[7] = (float)((cy + 6) % 12) * t12;
    pf[8] = (float)((cx + 6) % 12) * t12;
    float pe = pos_b[d];
#pragma unroll
    for (int f = 0; f < 9; f++) pe = fmaf(pf[f], pos_w[f * DD + d], pe);
    float val = vf[(size_t)j * DD + d] + pe;
    g_resid[(size_t)i * DD + d] = val;

    float v2 = val * val;
#pragma unroll
    for (int o = 16; o > 0; o >>= 1) v2 += __shfl_xor_sync(0xffffffffu, v2, o);
    __shared__ float red[4];
    if ((d & 31) == 0) red[d >> 5] = v2;
    __syncthreads();
    float ms = (red[0] + red[1] + red[2] + red[3]) * (1.0f / 128.0f);
    g_rmsb[(size_t)i * DD + d] = __float2bfloat16(val * rsqrtf(ms + EPSF) * rms_w[d]);
}

// ---------------- bf16 tensor-core GEMM, cp.async double-buffered -------------
// C[M,Nc] = A[M,Kd] @ B[Kd,Nc] (+S). A,B bf16 row-major; C,S fp32.
// 256 threads = 8 warps (4 x 2). BM = MT*64, BN = 64, BK = 32.
template <int MT, bool ADD>
__global__ void bgemm(const __nv_bfloat16* __restrict__ A, const __nv_bfloat16* __restrict__ B,
                      const float* __restrict__ S, float* __restrict__ C, int Nc, int Kd) {
    constexpr int BM = MT * 64;
    constexpr int BK = 32;
    constexpr int LDA = 112;  // bytes/row: 64B data + pad; 28 words -> conflict-free, 16B mult
    constexpr int LDB = 144;  // bytes/row: 128B data + pad; 36 words -> conflict-free, 16B mult
    __shared__ __align__(16) unsigned char As[2][BM * LDA];
    __shared__ __align__(16) unsigned char Bs[2][BK * LDB];
    int tid = threadIdx.x;
    int lane = tid & 31;
    int warp = tid >> 5;
    int wr = warp & 3;
    int wc = warp >> 2;
    long row0 = (long)blockIdx.x * BM;
    int col0 = blockIdx.y * 64;

    float acc[MT][4][4];
#pragma unroll
    for (int m = 0; m < MT; m++)
#pragma unroll
        for (int n = 0; n < 4; n++)
#pragma unroll
            for (int r = 0; r < 4; r++) acc[m][n][r] = 0.0f;

    uint32_t asb[2], bsb[2];
    asb[0] = (uint32_t)__cvta_generic_to_shared(&As[0][0]);
    asb[1] = (uint32_t)__cvta_generic_to_shared(&As[1][0]);
    bsb[0] = (uint32_t)__cvta_generic_to_shared(&Bs[0][0]);
    bsb[1] = (uint32_t)__cvta_generic_to_shared(&Bs[1][0]);

    // per-thread copy coords
    int ar = 0, ac = 0;  // A: MT chunks of 16B
    ar = tid >> 2;
    ac = tid & 3;
    int br = tid >> 3;
    int bc = tid & 7;

    auto issue = [&](int buf, int k0) {
#pragma unroll
        for (int it = 0; it < MT; it++) {
            int r = ar + it * 64;
            cpa16(asb[buf] + r * LDA + ac * 16, A + (row0 + r) * Kd + k0 + ac * 8);
        }
        cpa16(bsb[buf] + br * LDB + bc * 16, B + (long)(k0 + br) * Nc + col0 + bc * 8);
        cp_commit();
    };

    int KT = Kd / BK;
    issue(0, 0);
    int buf = 0;

    int a_row_in_tile = lane & 15;
    int a_colh = (lane >> 4) << 3;
    int b_krow = (lane & 7) + (((lane >> 3) & 1) << 3);
    int b_ncol = (lane >> 4) << 3;

    for (int kt = 0; kt < KT; kt++) {
        if (kt + 1 < KT) {
            issue(buf ^ 1, (kt + 1) * BK);
            cp_wait<1>();
        } else {
            cp_wait<0>();
        }
        __syncthreads();
#pragma unroll
        for (int ks = 0; ks < 2; ks++) {
            int kh = ks * 16;
            uint32_t a[MT][4];
#pragma unroll
            for (int mt = 0; mt < MT; mt++) {
                int row = wr * (MT * 16) + mt * 16 + a_row_in_tile;
                ldsm4(a[mt][0], a[mt][1], a[mt][2], a[mt][3],
                      asb[buf] + row * LDA + (kh + a_colh) * 2);
            }
            uint32_t b[4][2];
#pragma unroll
            for (int np = 0; np < 2; np++) {
                int krow = kh + b_krow;
                int ncol = wc * 32 + np * 16 + b_ncol;
                uint32_t r0, r1, r2, r3;
                ldsm4t(r0, r1, r2, r3, bsb[buf] + krow * LDB + ncol * 2);
                b[np * 2][0] = r0;
                b[np * 2][1] = r1;
                b[np * 2 + 1][0] = r2;
                b[np * 2 + 1][1] = r3;
            }
#pragma unroll
            for (int mt = 0; mt < MT; mt++)
#pragma unroll
                for (int nt = 0; nt < 4; nt++) mma_bf16(acc[mt][nt], a[mt], b[nt]);
        }
        __syncthreads();
        buf ^= 1;
    }

    int g = lane >> 2;
    int tg = lane & 3;
#pragma unroll
    for (int mt = 0; mt < MT; mt++) {
#pragma unroll
        for (int nt = 0; nt < 4; nt++) {
            long r0 = row0 + wr * (MT * 16) + mt * 16 + g;
            int c = col0 + wc * 32 + nt * 8 + tg * 2;
            float2 v0 = make_float2(acc[mt][nt][0], acc[mt][nt][1]);
            float2 v1 = make_float2(acc[mt][nt][2], acc[mt][nt][3]);
            if (ADD) {
                float2 s0 = *(const float2*)(S + r0 * Nc + c);
                float2 s1 = *(const float2*)(S + (r0 + 8) * Nc + c);
                v0.x += s0.x; v0.y += s0.y;
                v1.x += s1.x; v1.y += s1.y;
            }
            *(float2*)(C + r0 * Nc + c) = v0;
            *(float2*)(C + (r0 + 8) * Nc + c) = v1;
        }
    }
}

// ---------------- kernel 3: causal conv (K=4) + bias + silu -------------------
__global__ void k_conv(const float* __restrict__ conv_w, const float* __restrict__ conv_b) {
    int idx = blockIdx.x * blockDim.x + threadIdx.x;
    int tb = idx >> 8;
    int c = idx & 255;
    int t0 = tb * 8;
    float w0 = conv_w[c * 4 + 0], w1 = conv_w[c * 4 + 1];
    float w2 = conv_w[c * 4 + 2], w3 = conv_w[c * 4 + 3];
    float bias = conv_b[c];
    float v[11];
#pragma unroll
    for (int i = 0; i < 11; i++) {
        int t = t0 - 3 + i;
        v[i] = (t >= 0) ? g_xz[(size_t)t * 512 + c] : 0.0f;
    }
#pragma unroll
    for (int j = 0; j < 8; j++) {
        float s = bias;
        s = fmaf(w0, v[j], s);
        s = fmaf(w1, v[j + 1], s);
        s = fmaf(w2, v[j + 2], s);
        s = fmaf(w3, v[j + 3], s);
        float r = silu_f(s);
        g_xc[(size_t)(t0 + j) * DIc + c] = r;
        g_xcb[(size_t)(t0 + j) * DIc + c] = __float2bfloat16(r);
    }
}

// ---------------- kernel 5: fused dt(softplus) + B/C extract ------------------
__global__ void k_dtbc(const float* __restrict__ dtw, const float* __restrict__ dtb) {
    int idx = blockIdx.x * blockDim.x + threadIdx.x;  // N*64
    int t = idx >> 6;
    int j = idx & 63;
    int c4 = j * 4;
    float4 d0 = *(const float4*)(g_dbc + (size_t)t * 64);
    float4 d1 = *(const float4*)(g_dbc + (size_t)t * 64 + 4);
    float u[8] = {d0.x, d0.y, d0.z, d0.w, d1.x, d1.y, d1.z, d1.w};
    float4 acc = *(const float4*)(dtb + c4);
#pragma unroll
    for (int k = 0; k < 8; k++) {
        float4 w = *(const float4*)(dtw + k * DIc + c4);
        acc.x = fmaf(u[k], w.x, acc.x);
        acc.y = fmaf(u[k], w.y, acc.y);
        acc.z = fmaf(u[k], w.z, acc.z);
        acc.w = fmaf(u[k], w.w, acc.w);
    }
    acc.x = softplus_f(acc.x);
    acc.y = softplus_f(acc.y);
    acc.z = softplus_f(acc.z);
    acc.w = softplus_f(acc.w);
    *(float4*)(g_dt + (size_t)t * DIc + c4) = acc;
    if (j < 4) {
        *(float4*)(g_Bm + (size_t)t * 16 + j * 4) =
            *(const float4*)(g_dbc + (size_t)t * 64 + 8 + j * 4);
    } else if (j < 8) {
        *(float4*)(g_Cm + (size_t)t * 16 + (j - 4) * 4) =
            *(const float4*)(g_dbc + (size_t)t * 64 + 24 + (j - 4) * 4);
    }
}

// ---------------- kernel 7: scan pass 1 ---------------------------------------
__global__ void k_scan1(const float* __restrict__ A_log) {
    int chunk = blockIdx.x;
    int c = threadIdx.x;
    __shared__ float Bs[LC][DSc];
    int t0 = chunk * LC;
    for (int i = threadIdx.x; i < LC * DSc; i += blockDim.x)
        Bs[i / DSc][i % DSc] = g_Bm[(size_t)t0 * DSc + i];
    __syncthreads();
    float A2[DSc];
#pragma unroll
    for (int s = 0; s < DSc; s++) A2[s] = -__expf(A_log[c * DSc + s]) * LOG2E;
    float base = A2[0];
    bool structured = true;
#pragma unroll
    for (int s = 0; s < DSc; s++) {
        float e = base * (float)(s + 1);
        structured = structured && (fabsf(A2[s] - e) <= 1e-5f * fabsf(e) + 1e-30f);
    }
    float h[DSc];
#pragma unroll
    for (int s = 0; s < DSc; s++) h[s] = 0.0f;
    float sdt = 0.0f;
    if (structured) {
#pragma unroll 2
        for (int t = 0; t < LC; t++) {
            float d = g_dt[(size_t)(t0 + t) * DIc + c];
            float x = g_xc[(size_t)(t0 + t) * DIc + c];
            float dx = d * x;
            sdt += d;
            float a[DSc];
            pow_chain(ex2(d * base), a);
#pragma unroll
            for (int s = 0; s < DSc; s++) h[s] = fmaf(a[s], h[s], dx * Bs[t][s]);
        }
    } else {
#pragma unroll 2
        for (int t = 0; t < LC; t++) {
            float d = g_dt[(size_t)(t0 + t) * DIc + c];
            float x = g_xc[(size_t)(t0 + t) * DIc + c];
            float dx = d * x;
            sdt += d;
#pragma unroll
            for (int s = 0; s < DSc; s++) {
                float a = ex2(d * A2[s]);
                h[s] = fmaf(a, h[s], dx * Bs[t][s]);
            }
        }
    }
    size_t o = ((size_t)chunk * DIc + c) * DSc;
#pragma unroll
    for (int s = 0; s < DSc; s++) {
        g_He[o + s] = h[s];
        g_P[o + s] = ex2(sdt * A2[s]);
    }
}

// ---------------- kernel 8: cross-chunk combine -------------------------------
__global__ void k_combine() {
    int idx = blockIdx.x * blockDim.x + threadIdx.x;
    float h = 0.0f;
    for (int k = 0; k < NCH; k++) {
        size_t o = (size_t)k * DIc * DSc + idx;
        g_Hin[o] = h;
        h = fmaf(g_P[o], h, g_He[o]);
    }
}

// ---------------- kernel 9: scan pass 2 (seeded replay + gate) ----------------
__global__ void k_scan2(const float* __restrict__ A_log, const float* __restrict__ Dskip) {
    int chunk = blockIdx.x;
    int c = threadIdx.x;
    __shared__ float Bs[LC][DSc];
    __shared__ float Cs[LC][DSc];
    int t0 = chunk * LC;
    for (int i = threadIdx.x; i < LC * DSc; i += blockDim.x) {
        Bs[i / DSc][i % DSc] = g_Bm[(size_t)t0 * DSc + i];
        Cs[i / DSc][i % DSc] = g_Cm[(size_t)t0 * DSc + i];
    }
    __syncthreads();
    float A2[DSc];
#pragma unroll
    for (int s = 0; s < DSc; s++) A2[s] = -__expf(A_log[c * DSc + s]) * LOG2E;
    float base = A2[0];
    bool structured = true;
#pragma unroll
    for (int s = 0; s < DSc; s++) {
        float e = base * (float)(s + 1);
        structured = structured && (fabsf(A2[s] - e) <= 1e-5f * fabsf(e) + 1e-30f);
    }
    float h[DSc];
    size_t oh = ((size_t)chunk * DIc + c) * DSc;
#pragma unroll
    for (int s = 0; s < DSc; s++) h[s] = g_Hin[oh + s];
    float dsk = Dskip[c];
    if (structured) {
#pragma unroll 2
        for (int t = 0; t < LC; t++) {
            float d = g_dt[(size_t)(t0 + t) * DIc + c];
            float x = g_xc[(size_t)(t0 + t) * DIc + c];
            float z = g_xz[(size_t)(t0 + t) * 512 + DIc + c];
            float dx = d * x;
            float a[DSc];
            pow_chain(ex2(d * base), a);
            float acc = 0.0f;
#pragma unroll
            for (int s = 0; s < DSc; s++) {
                h[s] = fmaf(a[s], h[s], dx * Bs[t][s]);
                acc = fmaf(h[s], Cs[t][s], acc);
            }
            acc = fmaf(dsk, x, acc);
            g_yb[(size_t)(t0 + t) * DIc + c] = __float2bfloat16(acc * silu_f(z));
        }
    } else {
#pragma unroll 2
        for (int t = 0; t < LC; t++) {
            float d = g_dt[(size_t)(t0 + t) * DIc + c];
            float x = g_xc[(size_t)(t0 + t) * DIc + c];
            float z = g_xz[(size_t)(t0 + t) * 512 + DIc + c];
            float dx = d * x;
            float acc = 0.0f;
#pragma unroll
            for (int s = 0; s < DSc; s++) {
                float a = ex2(d * A2[s]);
                h[s] = fmaf(a, h[s], dx * Bs[t][s]);
                acc = fmaf(h[s], Cs[t][s], acc);
            }
            acc = fmaf(dsk, x, acc);
            g_yb[(size_t)(t0 + t) * DIc + c] = __float2bfloat16(acc * silu_f(z));
        }
    }
}

// ---------------- kernel 11: inv_perm gather + LayerNorm ----------------------
__global__ void k_ln(const int* __restrict__ inv_perm, const float* __restrict__ ln_w,
                     const float* __restrict__ ln_b, float* __restrict__ out) {
    int i = blockIdx.x;
    int d = threadIdx.x;
    int j = inv_perm[i];
    float v = g_x2[(size_t)j * DD + d];
    float s1 = v, s2 = v * v;
#pragma unroll
    for (int o = 16; o > 0; o >>= 1) {
        s1 += __shfl_xor_sync(0xffffffffu, s1, o);
        s2 += __shfl_xor_sync(0xffffffffu, s2, o);
    }
    __shared__ float rA[4], rB[4];
    if ((d & 31) == 0) { rA[d >> 5] = s1; rB[d >> 5] = s2; }
    __syncthreads();
    float mu = (rA[0] + rA[1] + rA[2] + rA[3]) * (1.0f / 128.0f);
    float e2 = (rB[0] + rB[1] + rB[2] + rB[3]) * (1.0f / 128.0f);
    float var = e2 - mu * mu;
    out[(size_t)i * DD + d] = (v - mu) * rsqrtf(var + EPSF) * ln_w[d] + ln_b[d];
}

// ---------------- host ---------------------------------------------------------
extern "C" void kernel_launch(void* const* d_in, const int* in_sizes, int n_in,
                              void* d_out, int out_size) {
    const float *vf, *pos_w, *pos_b, *rms_w, *in_proj_w, *conv_w, *conv_b, *x_proj_w;
    const float *dt_w, *dt_b, *A_log, *Dskip, *out_proj_w, *ln_w, *ln_b;
    const int *coords, *perm, *inv_perm;

    if (in_sizes[1] == NN * 4) {
        vf = (const float*)d_in[0];
        coords = (const int*)d_in[1];
        perm = (const int*)d_in[2];
        inv_perm = (const int*)d_in[3];
        pos_w = (const float*)d_in[4];
        pos_b = (const float*)d_in[5];
        rms_w = (const float*)d_in[6];
        in_proj_w = (const float*)d_in[7];
        conv_w = (const float*)d_in[8];
        conv_b = (const float*)d_in[9];
        x_proj_w = (const float*)d_in[10];
        dt_w = (const float*)d_in[11];
        dt_b = (const float*)d_in[12];
        A_log = (const float*)d_in[13];
        Dskip = (const float*)d_in[14];
        out_proj_w = (const float*)d_in[15];
        ln_w = (const float*)d_in[16];
        ln_b = (const float*)d_in[17];
    } else {
        vf = (const float*)d_in[0];
        pos_w = (const float*)d_in[1];
        pos_b = (const float*)d_in[2];
        rms_w = (const float*)d_in[3];
        in_proj_w = (const float*)d_in[4];
        conv_w = (const float*)d_in[5];
        conv_b = (const float*)d_in[6];
        x_proj_w = (const float*)d_in[7];
        dt_w = (const float*)d_in[8];
        dt_b = (const float*)d_in[9];
        A_log = (const float*)d_in[10];
        Dskip = (const float*)d_in[11];
        out_proj_w = (const float*)d_in[12];
        ln_w = (const float*)d_in[13];
        ln_b = (const float*)d_in[14];
        coords = (const int*)d_in[15];
        perm = (const int*)d_in[16];
        inv_perm = (const int*)d_in[17];
    }

    void *p_rmsb, *p_xz, *p_xcb, *p_dbc, *p_yb, *p_x2, *p_resid, *p_w1b, *p_w2b, *p_w3b;
    cudaGetSymbolAddress(&p_rmsb, g_rmsb);
    cudaGetSymbolAddress(&p_xz, g_xz);
    cudaGetSymbolAddress(&p_xcb, g_xcb);
    cudaGetSymbolAddress(&p_dbc, g_dbc);
    cudaGetSymbolAddress(&p_yb, g_yb);
    cudaGetSymbolAddress(&p_x2, g_x2);
    cudaGetSymbolAddress(&p_resid, g_resid);
    cudaGetSymbolAddress(&p_w1b, g_w1b);
    cudaGetSymbolAddress(&p_w2b, g_w2b);
    cudaGetSymbolAddress(&p_w3b, g_w3b);

    k_wcvt<<<448, 256>>>(in_proj_w, x_proj_w, out_proj_w);
    k_pre<<<NN, 128>>>(vf, coords, perm, pos_w, pos_b, rms_w);
    // in_proj: xz[N,512] = rmsb[N,128] @ w1b[128,512]
    bgemm<2, false><<<dim3(NN / 128, 512 / 64), 256>>>(
        (const __nv_bfloat16*)p_rmsb, (const __nv_bfloat16*)p_w1b, nullptr, (float*)p_xz, 512,
        128);
    k_conv<<<(NN / 8), 256>>>(conv_w, conv_b);
    // x_proj: dbc[N,64] = xcb[N,256] @ w2b[256,64]
    bgemm<1, false><<<dim3(NN / 64, 1), 256>>>(
        (const __nv_bfloat16*)p_xcb, (const __nv_bfloat16*)p_w2b, nullptr, (float*)p_dbc, 64,
        256);
    k_dtbc<<<NN * 64 / 256, 256>>>(dt_w, dt_b);
    k_scan1<<<NCH, DIc>>>(A_log);
    k_combine<<<DIc * DSc / 256, 256>>>();
    k_scan2<<<NCH, DIc>>>(A_log, Dskip);
    // out_proj + residual: x2[N,128] = yb[N,256] @ w3b[256,128] + resid
    bgemm<2, true><<<dim3(NN / 128, DD / 64), 256>>>(
        (const __nv_bfloat16*)p_yb, (const __nv_bfloat16*)p_w3b, (const float*)p_resid,
        (float*)p_x2, DD, DIc);
    k_ln<<<NN, 128>>>(inv_perm, ln_w, ln_b, (float*)d_out);
    (void)n_in;
    (void)out_size;
    (void)in_sizes;
}

// round 10
// speedup vs baseline: 1.9417x; 1.3204x over previous
#include <cuda_runtime.h>
#include <cuda_bf16.h>
#include <cstdint>

#define NN 32768
#define DD 128
#define DIc 256
#define DSc 16
#define LC 128
#define NCH (NN / LC)
#define EPSF 1e-5f
#define LOG2E 1.4426950408889634f
#define LN2F 0.6931471805599453f

// ---------------- scratch (device globals; no allocation allowed) -------------
__device__ float g_resid[NN * DD];
__device__ __nv_bfloat16 g_rmsb[NN * DD];
__device__ __nv_bfloat16 g_xzb[NN * 2 * DIc];
__device__ __nv_bfloat16 g_xcb[NN * DIc];
__device__ float g_dbc[NN * 64];
__device__ float g_P[NCH * DIc * DSc];
__device__ float g_He[NCH * DIc * DSc];
__device__ float g_Hin[NCH * DIc * DSc];
__device__ __nv_bfloat16 g_yb[NN * DIc];
__device__ __nv_bfloat16 g_w1b[DD * 512];
__device__ __nv_bfloat16 g_w2b[DIc * 64];
__device__ __nv_bfloat16 g_w3b[DIc * DD];

// ---------------- helpers -----------------------------------------------------
__device__ __forceinline__ float ex2(float x) {
    float y;
    asm("ex2.approx.ftz.f32 %0, %1;" : "=f"(y) : "f"(x));
    return y;
}
__device__ __forceinline__ float lg2(float x) {
    float y;
    asm("lg2.approx.ftz.f32 %0, %1;" : "=f"(y) : "f"(x));
    return y;
}
__device__ __forceinline__ float fexp(float x) { return ex2(x * LOG2E); }
__device__ __forceinline__ float silu_f(float x) { return x / (1.0f + fexp(-x)); }
__device__ __forceinline__ float softplus_fast(float v) {
    float t = ex2(v * LOG2E);
    float r = LN2F * lg2(1.0f + t);
    return v > 20.0f ? v : r;
}
__device__ __forceinline__ void ldsm4(uint32_t& r0, uint32_t& r1, uint32_t& r2, uint32_t& r3,
                                      uint32_t a) {
    asm volatile("ldmatrix.sync.aligned.m8n8.x4.shared.b16 {%0,%1,%2,%3},[%4];"
                 : "=r"(r0), "=r"(r1), "=r"(r2), "=r"(r3)
                 : "r"(a));
}
__device__ __forceinline__ void ldsm4t(uint32_t& r0, uint32_t& r1, uint32_t& r2, uint32_t& r3,
                                       uint32_t a) {
    asm volatile("ldmatrix.sync.aligned.m8n8.x4.trans.shared.b16 {%0,%1,%2,%3},[%4];"
                 : "=r"(r0), "=r"(r1), "=r"(r2), "=r"(r3)
                 : "r"(a));
}
__device__ __forceinline__ void mma_bf16(float* c, const uint32_t* a, const uint32_t* b) {
    asm volatile(
        "mma.sync.aligned.m16n8k16.row.col.f32.bf16.bf16.f32 "
        "{%0,%1,%2,%3},{%4,%5,%6,%7},{%8,%9},{%0,%1,%2,%3};"
        : "+f"(c[0]), "+f"(c[1]), "+f"(c[2]), "+f"(c[3])
        : "r"(a[0]), "r"(a[1]), "r"(a[2]), "r"(a[3]), "r"(b[0]), "r"(b[1]));
}
__device__ __forceinline__ void cpa16(uint32_t s, const void* g) {
    asm volatile("cp.async.cg.shared.global [%0], [%1], 16;" ::"r"(s), "l"(g));
}
__device__ __forceinline__ void cp_commit() { asm volatile("cp.async.commit_group;"); }
template <int NG>
__device__ __forceinline__ void cp_wait() {
    asm volatile("cp.async.wait_group %0;" ::"n"(NG));
}
// r^(s+1) for s=0..15, log-depth
__device__ __forceinline__ void pow_chain(float r, float* a) {
    a[0] = r;
    a[1] = r * r;
    a[2] = a[1] * r;
    a[3] = a[1] * a[1];
    a[4] = a[3] * r;
    a[5] = a[2] * a[2];
    a[6] = a[5] * r;
    a[7] = a[3] * a[3];
    a[8] = a[7] * r;
    a[9] = a[4] * a[4];
    a[10] = a[9] * r;
    a[11] = a[5] * a[5];
    a[12] = a[11] * r;
    a[13] = a[6] * a[6];
    a[14] = a[13] * r;
    a[15] = a[7] * a[7];
}

// ---------------- kernel 0: convert weights to bf16 (+ pad x_proj) ------------
__global__ void k_wcvt(const float* __restrict__ w1, const float* __restrict__ xw,
                       const float* __restrict__ w3) {
    int idx = blockIdx.x * blockDim.x + threadIdx.x;
    if (idx < DD * 512) {
        g_w1b[idx] = __float2bfloat16(w1[idx]);
    } else if (idx < DD * 512 + DIc * 64) {
        int i = idx - DD * 512;
        int k = i >> 6, j = i & 63;
        g_w2b[i] = __float2bfloat16(j < 40 ? xw[k * 40 + j] : 0.0f);
    } else {
        int i = idx - DD * 512 - DIc * 64;
        g_w3b[i] = __float2bfloat16(w3[i]);
    }
}

// ---------------- kernel 1: pos-encode + gather(perm) + RMSNorm ---------------
__global__ void k_pre(const float* __restrict__ vf, const int* __restrict__ coords,
                      const int* __restrict__ perm, const float* __restrict__ pos_w,
                      const float* __restrict__ pos_b, const float* __restrict__ rms_w) {
    int i = blockIdx.x;
    int d = threadIdx.x;  // 128
    int j = perm[i];
    int cz = coords[j * 4 + 1];
    int cy = coords[j * 4 + 2];
    int cx = coords[j * 4 + 3];
    const float dnm = 1.0f / 43.0f;
    const float t12 = 1.0f / 12.0f;
    float pf[9];
    pf[0] = (float)cz * (1.0f / 16.0f);
    pf[1] = (float)(cy / 12) * dnm;
    pf[2] = (float)(cx / 12) * dnm;
    pf[3] = (float)(cy % 12) * t12;
    pf[4] = (float)(cx % 12) * t12;
    pf[5] = (float)((cy + 6) / 12) * dnm;
    pf[6] = (float)((cx + 6) / 12) * dnm;
    pf[7] = (float)((cy + 6) % 12) * t12;
    pf[8] = (float)((cx + 6) % 12) * t12;
    float pe = pos_b[d];
#pragma unroll
    for (int f = 0; f < 9; f++) pe = fmaf(pf[f], pos_w[f * DD + d], pe);
    float val = vf[(size_t)j * DD + d] + pe;
    g_resid[(size_t)i * DD + d] = val;

    float v2 = val * val;
#pragma unroll
    for (int o = 16; o > 0; o >>= 1) v2 += __shfl_xor_sync(0xffffffffu, v2, o);
    __shared__ float red[4];
    if ((d & 31) == 0) red[d >> 5] = v2;
    __syncthreads();
    float ms = (red[0] + red[1] + red[2] + red[3]) * (1.0f / 128.0f);
    g_rmsb[(size_t)i * DD + d] = __float2bfloat16(val * rsqrtf(ms + EPSF) * rms_w[d]);
}

// ---------------- bf16 TC GEMM, cp.async double-buffered ----------------------
// C[M,Nc] = A[M,Kd] @ B[Kd,Nc]. A,B bf16 row-major. OUTB: bf16 out, else fp32.
template <int MT, bool OUTB>
__global__ void bgemm(const __nv_bfloat16* __restrict__ A, const __nv_bfloat16* __restrict__ B,
                      void* __restrict__ Cout, int Nc, int Kd) {
    constexpr int BM = MT * 64;
    constexpr int BK = 32;
    constexpr int LDA = 112;
    constexpr int LDB = 144;
    __shared__ __align__(16) unsigned char As[2][BM * LDA];
    __shared__ __align__(16) unsigned char Bs[2][BK * LDB];
    int tid = threadIdx.x;
    int lane = tid & 31;
    int warp = tid >> 5;
    int wr = warp & 3;
    int wc = warp >> 2;
    long row0 = (long)blockIdx.x * BM;
    int col0 = blockIdx.y * 64;

    float acc[MT][4][4];
#pragma unroll
    for (int m = 0; m < MT; m++)
#pragma unroll
        for (int n = 0; n < 4; n++)
#pragma unroll
            for (int r = 0; r < 4; r++) acc[m][n][r] = 0.0f;

    uint32_t asb[2], bsb[2];
    asb[0] = (uint32_t)__cvta_generic_to_shared(&As[0][0]);
    asb[1] = (uint32_t)__cvta_generic_to_shared(&As[1][0]);
    bsb[0] = (uint32_t)__cvta_generic_to_shared(&Bs[0][0]);
    bsb[1] = (uint32_t)__cvta_generic_to_shared(&Bs[1][0]);

    int ar = tid >> 2, ac = tid & 3;
    int br = tid >> 3, bc = tid & 7;

    auto issue = [&](int buf, int k0) {
#pragma unroll
        for (int it = 0; it < MT; it++) {
            int r = ar + it * 64;
            cpa16(asb[buf] + r * LDA + ac * 16, A + (row0 + r) * Kd + k0 + ac * 8);
        }
        cpa16(bsb[buf] + br * LDB + bc * 16, B + (long)(k0 + br) * Nc + col0 + bc * 8);
        cp_commit();
    };

    int KT = Kd / BK;
    issue(0, 0);
    int buf = 0;

    int a_row_in_tile = lane & 15;
    int a_colh = (lane >> 4) << 3;
    int b_krow = (lane & 7) + (((lane >> 3) & 1) << 3);
    int b_ncol = (lane >> 4) << 3;

    for (int kt = 0; kt < KT; kt++) {
        if (kt + 1 < KT) {
            issue(buf ^ 1, (kt + 1) * BK);
            cp_wait<1>();
        } else {
            cp_wait<0>();
        }
        __syncthreads();
#pragma unroll
        for (int ks = 0; ks < 2; ks++) {
            int kh = ks * 16;
            uint32_t a[MT][4];
#pragma unroll
            for (int mt = 0; mt < MT; mt++) {
                int row = wr * (MT * 16) + mt * 16 + a_row_in_tile;
                ldsm4(a[mt][0], a[mt][1], a[mt][2], a[mt][3],
                      asb[buf] + row * LDA + (kh + a_colh) * 2);
            }
            uint32_t b[4][2];
#pragma unroll
            for (int np = 0; np < 2; np++) {
                int krow = kh + b_krow;
                int ncol = wc * 32 + np * 16 + b_ncol;
                uint32_t r0, r1, r2, r3;
                ldsm4t(r0, r1, r2, r3, bsb[buf] + krow * LDB + ncol * 2);
                b[np * 2][0] = r0;
                b[np * 2][1] = r1;
                b[np * 2 + 1][0] = r2;
                b[np * 2 + 1][1] = r3;
            }
#pragma unroll
            for (int mt = 0; mt < MT; mt++)
#pragma unroll
                for (int nt = 0; nt < 4; nt++) mma_bf16(acc[mt][nt], a[mt], b[nt]);
        }
        __syncthreads();
        buf ^= 1;
    }

    int g = lane >> 2;
    int tg = lane & 3;
#pragma unroll
    for (int mt = 0; mt < MT; mt++) {
#pragma unroll
        for (int nt = 0; nt < 4; nt++) {
            long r0 = row0 + wr * (MT * 16) + mt * 16 + g;
            int c = col0 + wc * 32 + nt * 8 + tg * 2;
            if (OUTB) {
                __nv_bfloat16* C = (__nv_bfloat16*)Cout;
                *(__nv_bfloat162*)(C + r0 * Nc + c) =
                    __float22bfloat162_rn(make_float2(acc[mt][nt][0], acc[mt][nt][1]));
                *(__nv_bfloat162*)(C + (r0 + 8) * Nc + c) =
                    __float22bfloat162_rn(make_float2(acc[mt][nt][2], acc[mt][nt][3]));
            } else {
                float* C = (float*)Cout;
                *(float2*)(C + r0 * Nc + c) = make_float2(acc[mt][nt][0], acc[mt][nt][1]);
                *(float2*)(C + (r0 + 8) * Nc + c) = make_float2(acc[mt][nt][2], acc[mt][nt][3]);
            }
        }
    }
}

// ---------------- kernel 3: causal conv (K=4) + bias + silu (bf16 in/out) -----
__global__ void k_conv(const float* __restrict__ conv_w, const float* __restrict__ conv_b) {
    int idx = blockIdx.x * blockDim.x + threadIdx.x;
    int tb = idx >> 8;
    int c = idx & 255;
    int t0 = tb * 8;
    float w0 = conv_w[c * 4 + 0], w1 = conv_w[c * 4 + 1];
    float w2 = conv_w[c * 4 + 2], w3 = conv_w[c * 4 + 3];
    float bias = conv_b[c];
    float v[11];
#pragma unroll
    for (int i = 0; i < 11; i++) {
        int t = t0 - 3 + i;
        v[i] = (t >= 0) ? __bfloat162float(g_xzb[(size_t)t * 512 + c]) : 0.0f;
    }
#pragma unroll
    for (int j = 0; j < 8; j++) {
        float s = bias;
        s = fmaf(w0, v[j], s);
        s = fmaf(w1, v[j + 1], s);
        s = fmaf(w2, v[j + 2], s);
        s = fmaf(w3, v[j + 3], s);
        g_xcb[(size_t)(t0 + j) * DIc + c] = __float2bfloat16(silu_f(s));
    }
}

// ---------------- kernel 7: scan pass 1 (inline dt; local scan) ---------------
__global__ void k_scan1(const float* __restrict__ A_log, const float* __restrict__ dtw,
                        const float* __restrict__ dtb) {
    int chunk = blockIdx.x;
    int c = threadIdx.x;
    __shared__ float U[LC][8];
    __shared__ float Bsh[LC][16];
    int t0 = chunk * LC;
    {
        int row = threadIdx.x >> 1, q = threadIdx.x & 1;
        *(float4*)&U[row][q * 4] = *(const float4*)(g_dbc + (size_t)(t0 + row) * 64 + q * 4);
#pragma unroll
        for (int it = 0; it < 2; it++) {
            int v = threadIdx.x + it * 256;
            int r2 = v >> 2, q2 = v & 3;
            *(float4*)&Bsh[r2][q2 * 4] =
                *(const float4*)(g_dbc + (size_t)(t0 + r2) * 64 + 8 + q2 * 4);
        }
    }
    __syncthreads();
    float w8[8];
#pragma unroll
    for (int k = 0; k < 8; k++) w8[k] = dtw[k * DIc + c];
    float b0 = dtb[c];
    float A2[DSc];
#pragma unroll
    for (int s = 0; s < DSc; s++) A2[s] = -__expf(A_log[c * DSc + s]) * LOG2E;
    float base = A2[0];
    bool structured = true;
#pragma unroll
    for (int s = 0; s < DSc; s++) {
        float e = base * (float)(s + 1);
        structured = structured && (fabsf(A2[s] - e) <= 1e-5f * fabsf(e) + 1e-30f);
    }
    float h[DSc];
#pragma unroll
    for (int s = 0; s < DSc; s++) h[s] = 0.0f;
    float sdt = 0.0f;
    if (structured) {
#pragma unroll 2
        for (int t = 0; t < LC; t++) {
            float dot = b0;
#pragma unroll
            for (int k = 0; k < 8; k++) dot = fmaf(w8[k], U[t][k], dot);
            float d = softplus_fast(dot);
            float x = __bfloat162float(g_xcb[(size_t)(t0 + t) * DIc + c]);
            float dx = d * x;
            sdt += d;
            float a[DSc];
            pow_chain(ex2(d * base), a);
#pragma unroll
            for (int s = 0; s < DSc; s++) h[s] = fmaf(a[s], h[s], dx * Bsh[t][s]);
        }
    } else {
#pragma unroll 2
        for (int t = 0; t < LC; t++) {
            float dot = b0;
#pragma unroll
            for (int k = 0; k < 8; k++) dot = fmaf(w8[k], U[t][k], dot);
            float d = softplus_fast(dot);
            float x = __bfloat162float(g_xcb[(size_t)(t0 + t) * DIc + c]);
            float dx = d * x;
            sdt += d;
#pragma unroll
            for (int s = 0; s < DSc; s++) {
                float a = ex2(d * A2[s]);
                h[s] = fmaf(a, h[s], dx * Bsh[t][s]);
            }
        }
    }
    size_t o = ((size_t)chunk * DIc + c) * DSc;
#pragma unroll
    for (int s = 0; s < DSc; s++) {
        g_He[o + s] = h[s];
        g_P[o + s] = ex2(sdt * A2[s]);
    }
}

// ---------------- kernel 8: cross-chunk combine -------------------------------
__global__ void k_combine() {
    int idx = blockIdx.x * blockDim.x + threadIdx.x;
    float h = 0.0f;
    for (int k = 0; k < NCH; k++) {
        size_t o = (size_t)k * DIc * DSc + idx;
        g_Hin[o] = h;
        h = fmaf(g_P[o], h, g_He[o]);
    }
}

// ---------------- kernel 9: scan pass 2 (inline dt; replay + gate) ------------
__global__ void k_scan2(const float* __restrict__ A_log, const float* __restrict__ dtw,
                        const float* __restrict__ dtb, const float* __restrict__ Dskip) {
    int chunk = blockIdx.x;
    int c = threadIdx.x;
    __shared__ float U[LC][8];
    __shared__ float Bsh[LC][16];
    __shared__ float Csh[LC][16];
    int t0 = chunk * LC;
    {
        int row = threadIdx.x >> 1, q = threadIdx.x & 1;
        *(float4*)&U[row][q * 4] = *(const float4*)(g_dbc + (size_t)(t0 + row) * 64 + q * 4);
#pragma unroll
        for (int it = 0; it < 2; it++) {
            int v = threadIdx.x + it * 256;
            int r2 = v >> 2, q2 = v & 3;
            *(float4*)&Bsh[r2][q2 * 4] =
                *(const float4*)(g_dbc + (size_t)(t0 + r2) * 64 + 8 + q2 * 4);
            *(float4*)&Csh[r2][q2 * 4] =
                *(const float4*)(g_dbc + (size_t)(t0 + r2) * 64 + 24 + q2 * 4);
        }
    }
    __syncthreads();
    float w8[8];
#pragma unroll
    for (int k = 0; k < 8; k++) w8[k] = dtw[k * DIc + c];
    float b0 = dtb[c];
    float A2[DSc];
#pragma unroll
    for (int s = 0; s < DSc; s++) A2[s] = -__expf(A_log[c * DSc + s]) * LOG2E;
    float base = A2[0];
    bool structured = true;
#pragma unroll
    for (int s = 0; s < DSc; s++) {
        float e = base * (float)(s + 1);
        structured = structured && (fabsf(A2[s] - e) <= 1e-5f * fabsf(e) + 1e-30f);
    }
    float h[DSc];
    size_t oh = ((size_t)chunk * DIc + c) * DSc;
#pragma unroll
    for (int s = 0; s < DSc; s++) h[s] = g_Hin[oh + s];
    float dsk = Dskip[c];
    if (structured) {
#pragma unroll 2
        for (int t = 0; t < LC; t++) {
            float dot = b0;
#pragma unroll
            for (int k = 0; k < 8; k++) dot = fmaf(w8[k], U[t][k], dot);
            float d = softplus_fast(dot);
            float x = __bfloat162float(g_xcb[(size_t)(t0 + t) * DIc + c]);
            float z = __bfloat162float(g_xzb[(size_t)(t0 + t) * 512 + DIc + c]);
            float dx = d * x;
            float a[DSc];
            pow_chain(ex2(d * base), a);
            float acc = 0.0f;
#pragma unroll
            for (int s = 0; s < DSc; s++) {
                h[s] = fmaf(a[s], h[s], dx * Bsh[t][s]);
                acc = fmaf(h[s], Csh[t][s], acc);
            }
            acc = fmaf(dsk, x, acc);
            g_yb[(size_t)(t0 + t) * DIc + c] = __float2bfloat16(acc * silu_f(z));
        }
    } else {
#pragma unroll 2
        for (int t = 0; t < LC; t++) {
            float dot = b0;
#pragma unroll
            for (int k = 0; k < 8; k++) dot = fmaf(w8[k], U[t][k], dot);
            float d = softplus_fast(dot);
            float x = __bfloat162float(g_xcb[(size_t)(t0 + t) * DIc + c]);
            float z = __bfloat162float(g_xzb[(size_t)(t0 + t) * 512 + DIc + c]);
            float dx = d * x;
            float acc = 0.0f;
#pragma unroll
            for (int s = 0; s < DSc; s++) {
                float a = ex2(d * A2[s]);
                h[s] = fmaf(a, h[s], dx * Bsh[t][s]);
                acc = fmaf(h[s], Csh[t][s], acc);
            }
            acc = fmaf(dsk, x, acc);
            g_yb[(size_t)(t0 + t) * DIc + c] = __float2bfloat16(acc * silu_f(z));
        }
    }
}

// ---------------- kernel 10: fused out_proj + residual + LN + scatter ---------
// BM=64, BN=128 (full row), BK=32, Kd=256. out[perm[r]] = LN(y[r]@W + resid[r])
__global__ void k_outln(const __nv_bfloat16* __restrict__ A, const __nv_bfloat16* __restrict__ B,
                        const float* __restrict__ resid, const int* __restrict__ perm,
                        const float* __restrict__ ln_w, const float* __restrict__ ln_b,
                        float* __restrict__ out) {
    constexpr int BK = 32, Kd = 256, Nc = 128;
    constexpr int LDA = 112;   // 64 rows x (64B data + pad)
    constexpr int LDB = 272;   // 32 rows x (256B data + pad)
    __shared__ __align__(16) unsigned char As[2][64 * LDA];
    __shared__ __align__(16) unsigned char Bs[2][BK * LDB];
    __shared__ float redA[64][2], redB[64][2];
    int tid = threadIdx.x;
    int lane = tid & 31;
    int warp = tid >> 5;
    int wr = warp & 3;
    int wc = warp >> 2;
    long row0 = (long)blockIdx.x * 64;

    float acc[8][4];
#pragma unroll
    for (int n = 0; n < 8; n++)
#pragma unroll
        for (int r = 0; r < 4; r++) acc[n][r] = 0.0f;

    uint32_t asb[2], bsb[2];
    asb[0] = (uint32_t)__cvta_generic_to_shared(&As[0][0]);
    asb[1] = (uint32_t)__cvta_generic_to_shared(&As[1][0]);
    bsb[0] = (uint32_t)__cvta_generic_to_shared(&Bs[0][0]);
    bsb[1] = (uint32_t)__cvta_generic_to_shared(&Bs[1][0]);

    int ar = tid >> 2, ac = tid & 3;
    int br = tid >> 3, bc = tid & 7;

    auto issue = [&](int buf, int k0) {
        cpa16(asb[buf] + ar * LDA + ac * 16, A + (row0 + ar) * Kd + k0 + ac * 8);
        cpa16(bsb[buf] + br * LDB + bc * 16, B + (long)(k0 + br) * Nc + bc * 8);
        cpa16(bsb[buf] + br * LDB + 128 + bc * 16, B + (long)(k0 + br) * Nc + 64 + bc * 8);
        cp_commit();
    };

    issue(0, 0);
    int buf = 0;
    int a_row_in_tile = lane & 15;
    int a_colh = (lane >> 4) << 3;
    int b_krow = (lane & 7) + (((lane >> 3) & 1) << 3);
    int b_ncol = (lane >> 4) << 3;

    constexpr int KT = Kd / BK;
    for (int kt = 0; kt < KT; kt++) {
        if (kt + 1 < KT) {
            issue(buf ^ 1, (kt + 1) * BK);
            cp_wait<1>();
        } else {
            cp_wait<0>();
        }
        __syncthreads();
#pragma unroll
        for (int ks = 0; ks < 2; ks++) {
            int kh = ks * 16;
            uint32_t a[4];
            {
                int row = wr * 16 + a_row_in_tile;
                ldsm4(a[0], a[1], a[2], a[3], asb[buf] + row * LDA + (kh + a_colh) * 2);
            }
            uint32_t b[8][2];
#pragma unroll
            for (int np = 0; np < 4; np++) {
                int krow = kh + b_krow;
                int ncol = wc * 64 + np * 16 + b_ncol;
                uint32_t r0, r1, r2, r3;
                ldsm4t(r0, r1, r2, r3, bsb[buf] + krow * LDB + ncol * 2);
                b[np * 2][0] = r0;
                b[np * 2][1] = r1;
                b[np * 2 + 1][0] = r2;
                b[np * 2 + 1][1] = r3;
            }
#pragma unroll
            for (int nt = 0; nt < 8; nt++) mma_bf16(acc[nt], a, b[nt]);
        }
        __syncthreads();
        buf ^= 1;
    }

    // ---- epilogue: +resid, rowwise LN, scatter to out[perm[r]]
    int g = lane >> 2;
    int tg = lane & 3;
    int rA = wr * 16 + g;       // local row
    int rB = rA + 8;
    float va[16], vb[16];
    float s1a = 0.f, s2a = 0.f, s1b = 0.f, s2b = 0.f;
#pragma unroll
    for (int nt = 0; nt < 8; nt++) {
        int cc = wc * 64 + nt * 8 + tg * 2;
        float2 sa = *(const float2*)(resid + (row0 + rA) * Nc + cc);
        float2 sb = *(const float2*)(resid + (row0 + rB) * Nc + cc);
        float x0 = acc[nt][0] + sa.x, x1 = acc[nt][1] + sa.y;
        float x2 = acc[nt][2] + sb.x, x3 = acc[nt][3] + sb.y;
        va[nt * 2] = x0; va[nt * 2 + 1] = x1;
        vb[nt * 2] = x2; vb[nt * 2 + 1] = x3;
        s1a += x0 + x1; s2a += x0 * x0 + x1 * x1;
        s1b += x2 + x3; s2b += x2 * x2 + x3 * x3;
    }
#pragma unroll
    for (int o = 1; o <= 2; o <<= 1) {
        s1a += __shfl_xor_sync(0xffffffffu, s1a, o);
        s2a += __shfl_xor_sync(0xffffffffu, s2a, o);
        s1b += __shfl_xor_sync(0xffffffffu, s1b, o);
        s2b += __shfl_xor_sync(0xffffffffu, s2b, o);
    }
    if (tg == 0) {
        redA[rA][wc] = s1a; redB[rA][wc] = s2a;
        redA[rB][wc] = s1b; redB[rB][wc] = s2b;
    }
    __syncthreads();
    float muA = (redA[rA][0] + redA[rA][1]) * (1.0f / 128.0f);
    float e2A = (redB[rA][0] + redB[rA][1]) * (1.0f / 128.0f);
    float muB = (redA[rB][0] + redA[rB][1]) * (1.0f / 128.0f);
    float e2B = (redB[rB][0] + redB[rB][1]) * (1.0f / 128.0f);
    float rsA = rsqrtf(e2A - muA * muA + EPSF);
    float rsB = rsqrtf(e2B - muB * muB + EPSF);
    int prA = perm[row0 + rA];
    int prB = perm[row0 + rB];
#pragma unroll
    for (int nt = 0; nt < 8; nt++) {
        int cc = wc * 64 + nt * 8 + tg * 2;
        float2 w = *(const float2*)(ln_w + cc);
        float2 bb = *(const float2*)(ln_b + cc);
        float2 oa, ob;
        oa.x = (va[nt * 2] - muA) * rsA * w.x + bb.x;
        oa.y = (va[nt * 2 + 1] - muA) * rsA * w.y + bb.y;
        ob.x = (vb[nt * 2] - muB) * rsB * w.x + bb.x;
        ob.y = (vb[nt * 2 + 1] - muB) * rsB * w.y + bb.y;
        *(float2*)(out + (size_t)prA * Nc + cc) = oa;
        *(float2*)(out + (size_t)prB * Nc + cc) = ob;
    }
}

// ---------------- host ---------------------------------------------------------
extern "C" void kernel_launch(void* const* d_in, const int* in_sizes, int n_in,
                              void* d_out, int out_size) {
    const float *vf, *pos_w, *pos_b, *rms_w, *in_proj_w, *conv_w, *conv_b, *x_proj_w;
    const float *dt_w, *dt_b, *A_log, *Dskip, *out_proj_w, *ln_w, *ln_b;
    const int *coords, *perm, *inv_perm;

    if (in_sizes[1] == NN * 4) {
        vf = (const float*)d_in[0];
        coords = (const int*)d_in[1];
        perm = (const int*)d_in[2];
        inv_perm = (const int*)d_in[3];
        pos_w = (const float*)d_in[4];
        pos_b = (const float*)d_in[5];
        rms_w = (const float*)d_in[6];
        in_proj_w = (const float*)d_in[7];
        conv_w = (const float*)d_in[8];
        conv_b = (const float*)d_in[9];
        x_proj_w = (const float*)d_in[10];
        dt_w = (const float*)d_in[11];
        dt_b = (const float*)d_in[12];
        A_log = (const float*)d_in[13];
        Dskip = (const float*)d_in[14];
        out_proj_w = (const float*)d_in[15];
        ln_w = (const float*)d_in[16];
        ln_b = (const float*)d_in[17];
    } else {
        vf = (const float*)d_in[0];
        pos_w = (const float*)d_in[1];
        pos_b = (const float*)d_in[2];
        rms_w = (const float*)d_in[3];
        in_proj_w = (const float*)d_in[4];
        conv_w = (const float*)d_in[5];
        conv_b = (const float*)d_in[6];
        x_proj_w = (const float*)d_in[7];
        dt_w = (const float*)d_in[8];
        dt_b = (const float*)d_in[9];
        A_log = (const float*)d_in[10];
        Dskip = (const float*)d_in[11];
        out_proj_w = (const float*)d_in[12];
        ln_w = (const float*)d_in[13];
        ln_b = (const float*)d_in[14];
        coords = (const int*)d_in[15];
        perm = (const int*)d_in[16];
        inv_perm = (const int*)d_in[17];
    }
    (void)inv_perm;

    void *p_rmsb, *p_xzb, *p_xcb, *p_dbc, *p_yb, *p_resid, *p_w1b, *p_w2b, *p_w3b;
    cudaGetSymbolAddress(&p_rmsb, g_rmsb);
    cudaGetSymbolAddress(&p_xzb, g_xzb);
    cudaGetSymbolAddress(&p_xcb, g_xcb);
    cudaGetSymbolAddress(&p_dbc, g_dbc);
    cudaGetSymbolAddress(&p_yb, g_yb);
    cudaGetSymbolAddress(&p_resid, g_resid);
    cudaGetSymbolAddress(&p_w1b, g_w1b);
    cudaGetSymbolAddress(&p_w2b, g_w2b);
    cudaGetSymbolAddress(&p_w3b, g_w3b);

    k_wcvt<<<448, 256>>>(in_proj_w, x_proj_w, out_proj_w);
    k_pre<<<NN, 128>>>(vf, coords, perm, pos_w, pos_b, rms_w);
    // in_proj -> bf16 xz
    bgemm<2, true><<<dim3(NN / 128, 512 / 64), 256>>>(
        (const __nv_bfloat16*)p_rmsb, (const __nv_bfloat16*)p_w1b, p_xzb, 512, 128);
    k_conv<<<(NN / 8), 256>>>(conv_w, conv_b);
    // x_proj -> fp32 dbc
    bgemm<1, false><<<dim3(NN / 64, 1), 256>>>(
        (const __nv_bfloat16*)p_xcb, (const __nv_bfloat16*)p_w2b, p_dbc, 64, 256);
    k_scan1<<<NCH, DIc>>>(A_log, dt_w, dt_b);
    k_combine<<<DIc * DSc / 256, 256>>>();
    k_scan2<<<NCH, DIc>>>(A_log, dt_w, dt_b, Dskip);
    // fused out_proj + residual + LN + scatter
    k_outln<<<NN / 64, 256>>>((const __nv_bfloat16*)p_yb, (const __nv_bfloat16*)p_w3b,
                              (const float*)p_resid, perm, ln_w, ln_b, (float*)d_out);
    (void)n_in;
    (void)out_size;
    (void)in_sizes;
}